// round 1
// baseline (speedup 1.0000x reference)
#include <cuda_runtime.h>
#include <math.h>

#define Bb 4
#define SS 1025
#define LL 1024
#define EE 1024
#define HH 16
#define DH 64
#define EPSV 1e-5f

#define MT 16   // attention rows per block
#define JT 64   // key tile

// ---------------- scratch (static device globals; no allocs allowed) -------
__device__ float g_Q [Bb*LL*EE];
__device__ float g_K [Bb*LL*EE];
__device__ float g_V [Bb*LL*EE];
__device__ float g_Cp[Bb*LL*EE];
__device__ float g_vals[Bb*SS*EE];
__device__ float g_qn2[Bb*LL*HH];
__device__ float g_c  [Bb*EE];
__device__ float g_cn2[Bb*HH];
__device__ float g_cq [Bb*HH*LL];

// ---------------- generic NT SGEMM: Y[m][n] = sum_k A(m)[k]*W[n][k] + b[n] --
// amode 0: A row m -> x + (b*1025 + t + 1)*1024  (skip cls row per batch)
// amode 1: A row m -> A + m*1024
__global__ void sgemm_nt(const float* __restrict__ A, int amode,
                         const float* __restrict__ W,
                         const float* __restrict__ bias,
                         float* __restrict__ Y, int M)
{
    __shared__ float As[16][68];
    __shared__ float Bs[16][68];
    int tid = threadIdx.x;
    int tx = tid & 15, ty = tid >> 4;
    int m0 = blockIdx.x * 64, n0 = blockIdx.y * 64;

    int lr = tid >> 2;              // 0..63
    int lk = (tid & 3) << 2;        // 0,4,8,12

    int m = m0 + lr;
    bool mv = (m < M);
    const float* arow = A;
    if (mv) {
        if (amode == 0) { int b = m >> 10; int t = m & 1023; arow = A + (size_t)(b*SS + t + 1)*EE; }
        else            { arow = A + (size_t)m*EE; }
    }
    const float* wrow = W + (size_t)(n0 + lr)*EE;

    float acc[4][4];
    #pragma unroll
    for (int r = 0; r < 4; r++)
        #pragma unroll
        for (int c = 0; c < 4; c++) acc[r][c] = 0.f;

    for (int k0 = 0; k0 < EE; k0 += 16) {
        float4 av = mv ? *(const float4*)(arow + k0 + lk) : make_float4(0.f,0.f,0.f,0.f);
        float4 wv = *(const float4*)(wrow + k0 + lk);
        As[lk+0][lr] = av.x; As[lk+1][lr] = av.y; As[lk+2][lr] = av.z; As[lk+3][lr] = av.w;
        Bs[lk+0][lr] = wv.x; Bs[lk+1][lr] = wv.y; Bs[lk+2][lr] = wv.z; Bs[lk+3][lr] = wv.w;
        __syncthreads();
        #pragma unroll
        for (int kk = 0; kk < 16; kk++) {
            float4 a  = *(const float4*)&As[kk][ty*4];
            float4 bv = *(const float4*)&Bs[kk][tx*4];
            acc[0][0] += a.x*bv.x; acc[0][1] += a.x*bv.y; acc[0][2] += a.x*bv.z; acc[0][3] += a.x*bv.w;
            acc[1][0] += a.y*bv.x; acc[1][1] += a.y*bv.y; acc[1][2] += a.y*bv.z; acc[1][3] += a.y*bv.w;
            acc[2][0] += a.z*bv.x; acc[2][1] += a.z*bv.y; acc[2][2] += a.z*bv.z; acc[2][3] += a.z*bv.w;
            acc[3][0] += a.w*bv.x; acc[3][1] += a.w*bv.y; acc[3][2] += a.w*bv.z; acc[3][3] += a.w*bv.w;
        }
        __syncthreads();
    }

    float4 bv = *(const float4*)(bias + n0 + tx*4);
    #pragma unroll
    for (int r = 0; r < 4; r++) {
        int mm = m0 + ty*4 + r;
        if (mm < M) {
            float4 o = make_float4(acc[r][0]+bv.x, acc[r][1]+bv.y, acc[r][2]+bv.z, acc[r][3]+bv.w);
            *(float4*)(Y + (size_t)mm*EE + n0 + tx*4) = o;
        }
    }
}

// ---------------- cls query projection: c = x[b,0,:] @ Wq^T + bq -----------
__global__ void cls_proj_kernel(const float* __restrict__ x,
                                const float* __restrict__ Wq,
                                const float* __restrict__ bq)
{
    int idx = blockIdx.x * blockDim.x + threadIdx.x;   // 0..4095
    int b = idx >> 10, n = idx & 1023;
    const float* xr = x + (size_t)b*SS*EE;
    const float* wr = Wq + (size_t)n*EE;
    float s = 0.f;
    for (int k = 0; k < EE; k += 4) {
        float4 xv = *(const float4*)(xr + k);
        float4 wv = *(const float4*)(wr + k);
        s += xv.x*wv.x + xv.y*wv.y + xv.z*wv.z + xv.w*wv.w;
    }
    g_c[idx] = s + bq[n];
}

// ---------------- c_norm2 (clipped) ---------------------------------------
__global__ void cn2_kernel()
{
    int t = threadIdx.x;              // 0..63 = b*16+h
    const float* c = g_c + (t >> 4)*EE + (t & 15)*DH;
    float s = 0.f;
    #pragma unroll
    for (int d = 0; d < DH; d++) s += c[d]*c[d];
    g_cn2[t] = fmaxf(s, EPSV);
}

// ---------------- q_norm2 (clipped) ---------------------------------------
__global__ void qn2_kernel()
{
    int idx = blockIdx.x * blockDim.x + threadIdx.x;   // 0..65535
    int bt = idx >> 4, h = idx & 15;
    const float* q = g_Q + (size_t)bt*EE + h*DH;
    float s = 0.f;
    #pragma unroll
    for (int d = 0; d < DH; d += 4) {
        float4 v = *(const float4*)(q + d);
        s += v.x*v.x + v.y*v.y + v.z*v.z + v.w*v.w;
    }
    g_qn2[idx] = fmaxf(s, EPSV);
}

// ---------------- cq[b,h,j] = c_bh . q_bhj --------------------------------
__global__ void cq_kernel()
{
    int idx = blockIdx.x * blockDim.x + threadIdx.x;   // 0..65535
    int bh = idx >> 10, j = idx & 1023;
    int b = bh >> 4, h = bh & 15;
    const float* c = g_c + (size_t)b*EE + h*DH;
    const float* q = g_Q + (size_t)(b*LL + j)*EE + h*DH;
    float s = 0.f;
    #pragma unroll
    for (int d = 0; d < DH; d += 4) {
        float4 cv = *(const float4*)(c + d);
        float4 qv = *(const float4*)(q + d);
        s += cv.x*qv.x + cv.y*qv.y + cv.z*qv.z + cv.w*qv.w;
    }
    g_cq[idx] = s;
}

// ---------------- o2c: cls row of vals ------------------------------------
__global__ void o2c_kernel()
{
    __shared__ float cs[64];
    __shared__ float ck[1024];
    __shared__ float red[256];
    int h = blockIdx.x, b = blockIdx.y;
    int bh = b*HH + h;
    int tid = threadIdx.x;

    if (tid < 64) cs[tid] = g_c[(size_t)b*EE + h*DH + tid];
    __syncthreads();

    float scale = rsqrtf(64.f * g_cn2[bh]);
    for (int j = tid; j < 1024; j += 256) {
        const float* kr = g_K + (size_t)(b*LL + j)*EE + h*DH;
        float s = 0.f;
        #pragma unroll
        for (int d = 0; d < DH; d += 4) {
            float4 cv = *(const float4*)(cs + d);
            float4 kv = *(const float4*)(kr + d);
            s += cv.x*kv.x + cv.y*kv.y + cv.z*kv.z + cv.w*kv.w;
        }
        ck[j] = s * scale;
    }
    __syncthreads();

    float m = -1e30f;
    for (int j = tid; j < 1024; j += 256) m = fmaxf(m, ck[j]);
    red[tid] = m; __syncthreads();
    for (int s = 128; s > 0; s >>= 1) { if (tid < s) red[tid] = fmaxf(red[tid], red[tid+s]); __syncthreads(); }
    m = red[0]; __syncthreads();

    float l = 0.f;
    for (int j = tid; j < 1024; j += 256) { float e = expf(ck[j] - m); ck[j] = e; l += e; }
    red[tid] = l; __syncthreads();
    for (int s = 128; s > 0; s >>= 1) { if (tid < s) red[tid] += red[tid+s]; __syncthreads(); }
    l = red[0]; __syncthreads();
    float invl = 1.f / l;

    int d = tid & 63, part = tid >> 6;
    float s = 0.f;
    for (int j = part; j < 1024; j += 4)
        s += ck[j] * g_V[(size_t)(b*LL + j)*EE + h*DH + d];
    red[tid] = s; __syncthreads();
    if (part == 0) {
        float tot = red[d] + red[64+d] + red[128+d] + red[192+d];
        g_vals[(size_t)b*SS*EE + h*DH + d] = tot * invl;   // row 0 = cls_out
    }
}

// ---------------- fused attention core ------------------------------------
__global__ void attn_kernel(float* __restrict__ attn_out)
{
    extern __shared__ float sm[];
    float* S    = sm;                       // MT*1024
    float* Ks   = S + MT*1024;              // JT*65
    float* Qs   = Ks + JT*65;               // MT*65
    float* Pt   = Qs + MT*65;               // MT*JT
    float* cqs  = Pt + MT*JT;               // 1024
    float* sA   = cqs + 1024;               // 16
    float* w2   = sA + MT;                  // 16
    float* m1s  = w2 + MT;
    float* il1s = m1s + MT;
    float* m2s  = il1s + MT;
    float* il2s = m2s + MT;

    int tid = threadIdx.x;
    int b = blockIdx.z, h = blockIdx.y, i0 = blockIdx.x * MT;
    int bh = b*HH + h;
    size_t base = (size_t)b*LL*EE + h*DH;

    for (int idx = tid; idx < MT*DH; idx += 256) {
        int i = idx >> 6, d = idx & 63;
        Qs[i*65 + d] = g_Q[base + (size_t)(i0+i)*EE + d];
    }
    for (int idx = tid; idx < 1024; idx += 256)
        cqs[idx] = g_cq[(size_t)bh*LL + idx];
    if (tid < MT) {
        float qn = g_qn2[(size_t)(b*LL + i0 + tid)*HH + h];
        float s = rsqrtf(64.f*qn);
        sA[tid] = s;
        w2[tid] = s * rsqrtf(qn * g_cn2[bh]);
    }
    __syncthreads();

    int wi = tid >> 5, lane = tid & 31;
    int iA = wi*2;

    // Phase 1: raw scores S[i][j] = q_i . k_j
    for (int jt = 0; jt < LL/JT; jt++) {
        for (int idx = tid; idx < JT*DH; idx += 256) {
            int j = idx >> 6, d = idx & 63;
            Ks[j*65 + d] = g_K[base + (size_t)(jt*JT + j)*EE + d];
        }
        __syncthreads();
        float a00=0.f,a01=0.f,a10=0.f,a11=0.f;
        const float* q0 = &Qs[iA*65];
        const float* q1 = &Qs[(iA+1)*65];
        const float* k0 = &Ks[lane*65];
        const float* k1 = &Ks[(lane+32)*65];
        #pragma unroll 8
        for (int d = 0; d < 64; d++) {
            float qa = q0[d], qb = q1[d], ka = k0[d], kb = k1[d];
            a00 += qa*ka; a01 += qa*kb; a10 += qb*ka; a11 += qb*kb;
        }
        S[iA*1024     + jt*JT + lane]      = a00;
        S[iA*1024     + jt*JT + lane + 32] = a01;
        S[(iA+1)*1024 + jt*JT + lane]      = a10;
        S[(iA+1)*1024 + jt*JT + lane + 32] = a11;
        __syncthreads();
    }

    // Phase 2: dual softmax stats + attn output (warp per row, 2 rows each)
    for (int rr = 0; rr < 2; rr++) {
        int i = wi + rr*8;
        float sa = sA[i], ww = w2[i];
        const float* Srow = &S[i*1024];
        float m1 = -1e30f, mm2 = -1e30f;
        for (int j = lane; j < 1024; j += 32) {
            float r = Srow[j];
            m1  = fmaxf(m1,  r*sa);
            mm2 = fmaxf(mm2, r*cqs[j]);
        }
        #pragma unroll
        for (int o = 16; o > 0; o >>= 1) {
            m1  = fmaxf(m1,  __shfl_xor_sync(0xffffffffu, m1,  o));
            mm2 = fmaxf(mm2, __shfl_xor_sync(0xffffffffu, mm2, o));
        }
        float m2 = mm2 * ww;
        float l1 = 0.f, l2 = 0.f;
        for (int j = lane; j < 1024; j += 32) {
            float r = Srow[j];
            l1 += expf(r*sa - m1);
            l2 += expf(r*cqs[j]*ww - m2);
        }
        #pragma unroll
        for (int o = 16; o > 0; o >>= 1) {
            l1 += __shfl_xor_sync(0xffffffffu, l1, o);
            l2 += __shfl_xor_sync(0xffffffffu, l2, o);
        }
        float il1 = 1.f/l1, il2 = 1.f/l2;
        float* arow = attn_out + ((size_t)bh*LL + i0 + i)*LL;
        for (int j = lane; j < 1024; j += 32)
            arow[j] = expf(Srow[j]*sa - m1) * il1;
        if (lane == 0) { m1s[i]=m1; il1s[i]=il1; m2s[i]=m2; il2s[i]=il2; }
    }
    __syncthreads();

    // Phase 3: values = attn @ V + attn_c2o @ Cp   (shared accumulators)
    float acc0=0.f, acc1=0.f, acc2=0.f, acc3=0.f;
    int ii = tid >> 4;
    int dg = (tid & 15) * 4;
    for (int sub = 0; sub < 2; sub++) {
        const float* src = sub ? g_Cp : g_V;
        for (int jt = 0; jt < LL/JT; jt++) {
            __syncthreads();
            for (int idx = tid; idx < JT*DH; idx += 256) {
                int j = idx >> 6, d = idx & 63;
                Ks[j*65 + d] = src[base + (size_t)(jt*JT + j)*EE + d];
            }
            for (int idx = tid; idx < MT*JT; idx += 256) {
                int pi = idx >> 6, pj = idx & 63;
                float r = S[pi*1024 + jt*JT + pj];
                float p;
                if (sub == 0) p = expf(r*sA[pi] - m1s[pi]) * il1s[pi];
                else          p = expf(r*cqs[jt*JT + pj]*w2[pi] - m2s[pi]) * il2s[pi];
                Pt[idx] = p;
            }
            __syncthreads();
            const float* prow = &Pt[ii*JT];
            #pragma unroll 4
            for (int j = 0; j < JT; j++) {
                float p = prow[j];
                const float* kr = &Ks[j*65 + dg];
                acc0 += p*kr[0]; acc1 += p*kr[1]; acc2 += p*kr[2]; acc3 += p*kr[3];
            }
        }
    }
    float4 o = make_float4(acc0, acc1, acc2, acc3);
    *(float4*)&g_vals[((size_t)b*SS + 1 + i0 + ii)*EE + h*DH + dg] = o;
}

// ---------------- launch ----------------------------------------------------
extern "C" void kernel_launch(void* const* d_in, const int* in_sizes, int n_in,
                              void* d_out, int out_size)
{
    const float* x  = (const float*)d_in[0];
    const float* Wq = (const float*)d_in[1];
    const float* bq = (const float*)d_in[2];
    const float* Wk = (const float*)d_in[3];
    const float* bk = (const float*)d_in[4];
    const float* Wv = (const float*)d_in[5];
    const float* bv = (const float*)d_in[6];
    const float* Wo = (const float*)d_in[7];
    const float* bo = (const float*)d_in[8];
    const float* Wc = (const float*)d_in[9];
    const float* bc = (const float*)d_in[10];

    float* out  = (float*)d_out;                      // (B,1025,E)
    float* attn = out + (size_t)Bb*SS*EE;             // (B,H,1024,1024)

    float *dQ, *dK, *dV, *dCp, *dVals;
    cudaGetSymbolAddress((void**)&dQ,    g_Q);
    cudaGetSymbolAddress((void**)&dK,    g_K);
    cudaGetSymbolAddress((void**)&dV,    g_V);
    cudaGetSymbolAddress((void**)&dCp,   g_Cp);
    cudaGetSymbolAddress((void**)&dVals, g_vals);

    const int SMEM_BYTES = (MT*1024 + JT*65 + MT*65 + MT*JT + 1024 + 6*MT) * sizeof(float);
    cudaFuncSetAttribute(attn_kernel, cudaFuncAttributeMaxDynamicSharedMemorySize, SMEM_BYTES);

    dim3 gProj(64, 16);
    sgemm_nt<<<gProj, 256>>>(x, 0, Wq, bq, dQ,  Bb*LL);
    sgemm_nt<<<gProj, 256>>>(x, 0, Wk, bk, dK,  Bb*LL);
    sgemm_nt<<<gProj, 256>>>(x, 0, Wv, bv, dV,  Bb*LL);
    sgemm_nt<<<gProj, 256>>>(x, 0, Wc, bc, dCp, Bb*LL);

    cls_proj_kernel<<<16, 256>>>(x, Wq, bq);
    cn2_kernel<<<1, 64>>>();
    qn2_kernel<<<256, 256>>>();
    cq_kernel<<<256, 256>>>();
    o2c_kernel<<<dim3(HH, Bb), 256>>>();

    attn_kernel<<<dim3(LL/MT, HH, Bb), 256, SMEM_BYTES>>>(attn);

    dim3 gOut((Bb*SS + 63) / 64, 16);
    sgemm_nt<<<gOut, 256>>>(dVals, 1, Wo, bo, out, Bb*SS);
}

// round 3
// speedup vs baseline: 1.5994x; 1.5994x over previous
#include <cuda_runtime.h>
#include <math.h>

#define Bb 4
#define SS 1025
#define LL 1024
#define EE 1024
#define HH 16
#define DH 64
#define EPSV 1e-5f

#define MT 16   // attention rows per block
#define JT 64   // key tile

// ---------------- scratch (static device globals; no allocs allowed) -------
__device__ float g_Q [Bb*LL*EE];
__device__ float g_K [Bb*LL*EE];
__device__ float g_V [Bb*LL*EE];
__device__ float g_Cp[Bb*LL*EE];
__device__ float g_vals[Bb*SS*EE];
__device__ float g_qn2[Bb*LL*HH];
__device__ float g_c  [Bb*EE];
__device__ float g_cn2[Bb*HH];
__device__ float g_cq [Bb*HH*LL];

// ---------------- tf32 helpers ---------------------------------------------
__device__ __forceinline__ unsigned f2tf32(float x) {
    unsigned r;
    asm("cvt.rna.tf32.f32 %0, %1;" : "=r"(r) : "f"(x));
    return r;
}

__device__ __forceinline__ void mma_tf32(float& c0, float& c1, float& c2, float& c3,
                                         unsigned a0, unsigned a1, unsigned a2, unsigned a3,
                                         unsigned b0, unsigned b1)
{
    asm volatile("mma.sync.aligned.m16n8k8.row.col.f32.tf32.tf32.f32 "
                 "{%0,%1,%2,%3}, {%4,%5,%6,%7}, {%8,%9}, {%0,%1,%2,%3};"
                 : "+f"(c0), "+f"(c1), "+f"(c2), "+f"(c3)
                 : "r"(a0), "r"(a1), "r"(a2), "r"(a3), "r"(b0), "r"(b1));
}

// ---------------- fused Q/K/V/Cp projections (tf32 tensor core) ------------
// C[4096][1024] = A[4096][1024] @ W[1024][1024]^T + bias, A = tokens (cls skipped)
// grid: (32, 64): x = m-tile (128 rows), y: (y>>4) selects weight, (y&15) = n-tile (64 cols)
__global__ __launch_bounds__(256) void proj4_tf32(
    const float* __restrict__ x,
    const float* __restrict__ Wq, const float* __restrict__ bq,
    const float* __restrict__ Wk, const float* __restrict__ bk,
    const float* __restrict__ Wv, const float* __restrict__ bv,
    const float* __restrict__ Wc, const float* __restrict__ bc)
{
    __shared__ unsigned As[128][36];
    __shared__ unsigned Bs[64][36];

    int tid = threadIdx.x;
    int m0 = blockIdx.x * 128;
    int y  = blockIdx.y;
    int which = y >> 4;
    int n0 = (y & 15) * 64;

    const float* W; const float* bias; float* dst;
    switch (which) {
        case 0:  W = Wq; bias = bq; dst = g_Q;  break;
        case 1:  W = Wk; bias = bk; dst = g_K;  break;
        case 2:  W = Wv; bias = bv; dst = g_V;  break;
        default: W = Wc; bias = bc; dst = g_Cp; break;
    }

    int warp = tid >> 5, lane = tid & 31;
    int wm = warp >> 1, wn = warp & 1;
    int gid = lane >> 2, tig = lane & 3;

    float acc[2][4][4];
    #pragma unroll
    for (int mi = 0; mi < 2; mi++)
        #pragma unroll
        for (int ni = 0; ni < 4; ni++)
            #pragma unroll
            for (int c = 0; c < 4; c++) acc[mi][ni][c] = 0.f;

    int lr = tid >> 3;          // 0..31
    int lk = (tid & 7) * 4;     // 0,4,...,28

    for (int k0 = 0; k0 < EE; k0 += 32) {
        #pragma unroll
        for (int r = 0; r < 4; r++) {
            int m = m0 + lr + r * 32;
            int b = m >> 10, t = m & 1023;
            float4 v = *(const float4*)(x + (size_t)(b * SS + t + 1) * EE + k0 + lk);
            As[lr + r * 32][lk + 0] = f2tf32(v.x);
            As[lr + r * 32][lk + 1] = f2tf32(v.y);
            As[lr + r * 32][lk + 2] = f2tf32(v.z);
            As[lr + r * 32][lk + 3] = f2tf32(v.w);
        }
        #pragma unroll
        for (int r = 0; r < 2; r++) {
            float4 v = *(const float4*)(W + (size_t)(n0 + lr + r * 32) * EE + k0 + lk);
            Bs[lr + r * 32][lk + 0] = f2tf32(v.x);
            Bs[lr + r * 32][lk + 1] = f2tf32(v.y);
            Bs[lr + r * 32][lk + 2] = f2tf32(v.z);
            Bs[lr + r * 32][lk + 3] = f2tf32(v.w);
        }
        __syncthreads();

        #pragma unroll
        for (int kk = 0; kk < 32; kk += 8) {
            unsigned a[2][4], bfr[4][2];
            #pragma unroll
            for (int mi = 0; mi < 2; mi++) {
                int mb = wm * 32 + mi * 16;
                a[mi][0] = As[mb + gid    ][kk + tig    ];
                a[mi][1] = As[mb + gid + 8][kk + tig    ];
                a[mi][2] = As[mb + gid    ][kk + tig + 4];
                a[mi][3] = As[mb + gid + 8][kk + tig + 4];
            }
            #pragma unroll
            for (int ni = 0; ni < 4; ni++) {
                int nb = wn * 32 + ni * 8;
                bfr[ni][0] = Bs[nb + gid][kk + tig    ];
                bfr[ni][1] = Bs[nb + gid][kk + tig + 4];
            }
            #pragma unroll
            for (int mi = 0; mi < 2; mi++)
                #pragma unroll
                for (int ni = 0; ni < 4; ni++)
                    mma_tf32(acc[mi][ni][0], acc[mi][ni][1], acc[mi][ni][2], acc[mi][ni][3],
                             a[mi][0], a[mi][1], a[mi][2], a[mi][3],
                             bfr[ni][0], bfr[ni][1]);
        }
        __syncthreads();
    }

    // epilogue
    #pragma unroll
    for (int mi = 0; mi < 2; mi++) {
        int row1 = m0 + wm * 32 + mi * 16 + gid;
        int row2 = row1 + 8;
        #pragma unroll
        for (int ni = 0; ni < 4; ni++) {
            int col = n0 + wn * 32 + ni * 8 + tig * 2;
            float b0v = bias[col], b1v = bias[col + 1];
            float2 o1 = make_float2(acc[mi][ni][0] + b0v, acc[mi][ni][1] + b1v);
            float2 o2 = make_float2(acc[mi][ni][2] + b0v, acc[mi][ni][3] + b1v);
            *(float2*)(dst + (size_t)row1 * EE + col) = o1;
            *(float2*)(dst + (size_t)row2 * EE + col) = o2;
        }
    }
}

// ---------------- fp32 NT SGEMM (kept for the output projection) ------------
__global__ void sgemm_nt(const float* __restrict__ A, int amode,
                         const float* __restrict__ W,
                         const float* __restrict__ bias,
                         float* __restrict__ Y, int M)
{
    __shared__ float As[16][68];
    __shared__ float Bs[16][68];
    int tid = threadIdx.x;
    int tx = tid & 15, ty = tid >> 4;
    int m0 = blockIdx.x * 64, n0 = blockIdx.y * 64;

    int lr = tid >> 2;
    int lk = (tid & 3) << 2;

    int m = m0 + lr;
    bool mv = (m < M);
    const float* arow = A;
    if (mv) {
        if (amode == 0) { int b = m >> 10; int t = m & 1023; arow = A + (size_t)(b*SS + t + 1)*EE; }
        else            { arow = A + (size_t)m*EE; }
    }
    const float* wrow = W + (size_t)(n0 + lr)*EE;

    float acc[4][4];
    #pragma unroll
    for (int r = 0; r < 4; r++)
        #pragma unroll
        for (int c = 0; c < 4; c++) acc[r][c] = 0.f;

    for (int k0 = 0; k0 < EE; k0 += 16) {
        float4 av = mv ? *(const float4*)(arow + k0 + lk) : make_float4(0.f,0.f,0.f,0.f);
        float4 wv = *(const float4*)(wrow + k0 + lk);
        As[lk+0][lr] = av.x; As[lk+1][lr] = av.y; As[lk+2][lr] = av.z; As[lk+3][lr] = av.w;
        Bs[lk+0][lr] = wv.x; Bs[lk+1][lr] = wv.y; Bs[lk+2][lr] = wv.z; Bs[lk+3][lr] = wv.w;
        __syncthreads();
        #pragma unroll
        for (int kk = 0; kk < 16; kk++) {
            float4 a  = *(const float4*)&As[kk][ty*4];
            float4 bv = *(const float4*)&Bs[kk][tx*4];
            acc[0][0] += a.x*bv.x; acc[0][1] += a.x*bv.y; acc[0][2] += a.x*bv.z; acc[0][3] += a.x*bv.w;
            acc[1][0] += a.y*bv.x; acc[1][1] += a.y*bv.y; acc[1][2] += a.y*bv.z; acc[1][3] += a.y*bv.w;
            acc[2][0] += a.z*bv.x; acc[2][1] += a.z*bv.y; acc[2][2] += a.z*bv.z; acc[2][3] += a.z*bv.w;
            acc[3][0] += a.w*bv.x; acc[3][1] += a.w*bv.y; acc[3][2] += a.w*bv.z; acc[3][3] += a.w*bv.w;
        }
        __syncthreads();
    }

    float4 bv = *(const float4*)(bias + n0 + tx*4);
    #pragma unroll
    for (int r = 0; r < 4; r++) {
        int mm = m0 + ty*4 + r;
        if (mm < M) {
            float4 o = make_float4(acc[r][0]+bv.x, acc[r][1]+bv.y, acc[r][2]+bv.z, acc[r][3]+bv.w);
            *(float4*)(Y + (size_t)mm*EE + n0 + tx*4) = o;
        }
    }
}

// ---------------- cls query projection: c = x[b,0,:] @ Wq^T + bq -----------
__global__ void cls_proj_kernel(const float* __restrict__ x,
                                const float* __restrict__ Wq,
                                const float* __restrict__ bq)
{
    int idx = blockIdx.x * blockDim.x + threadIdx.x;
    int b = idx >> 10, n = idx & 1023;
    const float* xr = x + (size_t)b*SS*EE;
    const float* wr = Wq + (size_t)n*EE;
    float s = 0.f;
    for (int k = 0; k < EE; k += 4) {
        float4 xv = *(const float4*)(xr + k);
        float4 wv = *(const float4*)(wr + k);
        s += xv.x*wv.x + xv.y*wv.y + xv.z*wv.z + xv.w*wv.w;
    }
    g_c[idx] = s + bq[n];
}

__global__ void cn2_kernel()
{
    int t = threadIdx.x;
    const float* c = g_c + (t >> 4)*EE + (t & 15)*DH;
    float s = 0.f;
    #pragma unroll
    for (int d = 0; d < DH; d++) s += c[d]*c[d];
    g_cn2[t] = fmaxf(s, EPSV);
}

__global__ void qn2_kernel()
{
    int idx = blockIdx.x * blockDim.x + threadIdx.x;
    int bt = idx >> 4, h = idx & 15;
    const float* q = g_Q + (size_t)bt*EE + h*DH;
    float s = 0.f;
    #pragma unroll
    for (int d = 0; d < DH; d += 4) {
        float4 v = *(const float4*)(q + d);
        s += v.x*v.x + v.y*v.y + v.z*v.z + v.w*v.w;
    }
    g_qn2[idx] = fmaxf(s, EPSV);
}

__global__ void cq_kernel()
{
    int idx = blockIdx.x * blockDim.x + threadIdx.x;
    int bh = idx >> 10, j = idx & 1023;
    int b = bh >> 4, h = bh & 15;
    const float* c = g_c + (size_t)b*EE + h*DH;
    const float* q = g_Q + (size_t)(b*LL + j)*EE + h*DH;
    float s = 0.f;
    #pragma unroll
    for (int d = 0; d < DH; d += 4) {
        float4 cv = *(const float4*)(c + d);
        float4 qv = *(const float4*)(q + d);
        s += cv.x*qv.x + cv.y*qv.y + cv.z*qv.z + cv.w*qv.w;
    }
    g_cq[idx] = s;
}

__global__ void o2c_kernel()
{
    __shared__ float cs[64];
    __shared__ float ck[1024];
    __shared__ float red[256];
    int h = blockIdx.x, b = blockIdx.y;
    int bh = b*HH + h;
    int tid = threadIdx.x;

    if (tid < 64) cs[tid] = g_c[(size_t)b*EE + h*DH + tid];
    __syncthreads();

    float scale = rsqrtf(64.f * g_cn2[bh]);
    for (int j = tid; j < 1024; j += 256) {
        const float* kr = g_K + (size_t)(b*LL + j)*EE + h*DH;
        float s = 0.f;
        #pragma unroll
        for (int d = 0; d < DH; d += 4) {
            float4 cv = *(const float4*)(cs + d);
            float4 kv = *(const float4*)(kr + d);
            s += cv.x*kv.x + cv.y*kv.y + cv.z*kv.z + cv.w*kv.w;
        }
        ck[j] = s * scale;
    }
    __syncthreads();

    float m = -1e30f;
    for (int j = tid; j < 1024; j += 256) m = fmaxf(m, ck[j]);
    red[tid] = m; __syncthreads();
    for (int s = 128; s > 0; s >>= 1) { if (tid < s) red[tid] = fmaxf(red[tid], red[tid+s]); __syncthreads(); }
    m = red[0]; __syncthreads();

    float l = 0.f;
    for (int j = tid; j < 1024; j += 256) { float e = __expf(ck[j] - m); ck[j] = e; l += e; }
    red[tid] = l; __syncthreads();
    for (int s = 128; s > 0; s >>= 1) { if (tid < s) red[tid] += red[tid+s]; __syncthreads(); }
    l = red[0]; __syncthreads();
    float invl = 1.f / l;

    int d = tid & 63, part = tid >> 6;
    float s = 0.f;
    for (int j = part; j < 1024; j += 4)
        s += ck[j] * g_V[(size_t)(b*LL + j)*EE + h*DH + d];
    red[tid] = s; __syncthreads();
    if (part == 0) {
        float tot = red[d] + red[64+d] + red[128+d] + red[192+d];
        g_vals[(size_t)b*SS*EE + h*DH + d] = tot * invl;
    }
}

// ---------------- fused attention core ------------------------------------
__global__ __launch_bounds__(256) void attn_kernel(float* __restrict__ attn_out)
{
    extern __shared__ float sm[];
    float* S    = sm;                       // 16*1024
    float* U    = S + MT*1024;              // 5632 floats (union region)
    float* cqs  = U + 5632;                 // 1024
    float* sA   = cqs + 1024;               // 16
    float* w2   = sA + MT;                  // 16
    float* m1s  = w2 + MT;
    float* il1s = m1s + MT;
    float* m2s  = il1s + MT;
    float* il2s = m2s + MT;

    // phase-1 view of the union
    float* Ks = U;              // [64][65]
    float* Qs = U + 64*65;      // [16][65]
    // phase-3 view of the union
    float* Ts = U;              // [64][68]
    float* Pt = U + 64*68;      // [64][20]

    int tid = threadIdx.x;
    int b = blockIdx.z, h = blockIdx.y, i0 = blockIdx.x * MT;
    int bh = b*HH + h;
    size_t base = (size_t)b*LL*EE + h*DH;

    for (int idx = tid; idx < MT*DH; idx += 256) {
        int i = idx >> 6, d = idx & 63;
        Qs[i*65 + d] = g_Q[base + (size_t)(i0+i)*EE + d];
    }
    for (int idx = tid; idx < 1024; idx += 256)
        cqs[idx] = g_cq[(size_t)bh*LL + idx];
    if (tid < MT) {
        float qn = g_qn2[(size_t)(b*LL + i0 + tid)*HH + h];
        float s = rsqrtf(64.f*qn);
        sA[tid] = s;
        w2[tid] = s * rsqrtf(qn * g_cn2[bh]);
    }
    __syncthreads();

    int wi = tid >> 5, lane = tid & 31;
    int iA = wi*2;

    // Phase 1: raw scores S[i][j] = q_i . k_j
    for (int jt = 0; jt < LL/JT; jt++) {
        for (int idx = tid; idx < JT*DH; idx += 256) {
            int j = idx >> 6, d = idx & 63;
            Ks[j*65 + d] = g_K[base + (size_t)(jt*JT + j)*EE + d];
        }
        __syncthreads();
        float a00=0.f,a01=0.f,a10=0.f,a11=0.f;
        const float* q0 = &Qs[iA*65];
        const float* q1 = &Qs[(iA+1)*65];
        const float* k0 = &Ks[lane*65];
        const float* k1 = &Ks[(lane+32)*65];
        #pragma unroll 8
        for (int d = 0; d < 64; d++) {
            float qa = q0[d], qb = q1[d], ka = k0[d], kb = k1[d];
            a00 += qa*ka; a01 += qa*kb; a10 += qb*ka; a11 += qb*kb;
        }
        S[iA*1024     + jt*JT + lane]      = a00;
        S[iA*1024     + jt*JT + lane + 32] = a01;
        S[(iA+1)*1024 + jt*JT + lane]      = a10;
        S[(iA+1)*1024 + jt*JT + lane + 32] = a11;
        __syncthreads();
    }

    // Phase 2: dual softmax stats + attn output (warp per row, 2 rows each)
    for (int rr = 0; rr < 2; rr++) {
        int i = wi + rr*8;
        float sa = sA[i], ww = w2[i];
        const float* Srow = &S[i*1024];
        float m1 = -1e30f, mm2 = -1e30f;
        for (int j = lane; j < 1024; j += 32) {
            float r = Srow[j];
            m1  = fmaxf(m1,  r*sa);
            mm2 = fmaxf(mm2, r*cqs[j]);
        }
        #pragma unroll
        for (int o = 16; o > 0; o >>= 1) {
            m1  = fmaxf(m1,  __shfl_xor_sync(0xffffffffu, m1,  o));
            mm2 = fmaxf(mm2, __shfl_xor_sync(0xffffffffu, mm2, o));
        }
        float m2 = mm2 * ww;
        float l1 = 0.f, l2 = 0.f;
        for (int j = lane; j < 1024; j += 32) {
            float r = Srow[j];
            l1 += __expf(r*sa - m1);
            l2 += __expf(r*cqs[j]*ww - m2);
        }
        #pragma unroll
        for (int o = 16; o > 0; o >>= 1) {
            l1 += __shfl_xor_sync(0xffffffffu, l1, o);
            l2 += __shfl_xor_sync(0xffffffffu, l2, o);
        }
        float il1 = 1.f/l1, il2 = 1.f/l2;
        float* arow = attn_out + ((size_t)bh*LL + i0 + i)*LL;
        for (int j = lane; j < 1024; j += 32)
            arow[j] = __expf(Srow[j]*sa - m1) * il1;
        if (lane == 0) { m1s[i]=m1; il1s[i]=il1; m2s[i]=m2; il2s[i]=il2; }
    }

    // Phase 3: values = attn @ V + attn_c2o @ Cp, register-tiled 4x4, 4-way j-split
    int jq  = tid >> 6;          // 0..3  (j quarter)
    int r4u = (tid >> 4) & 3;    // row group (4 rows)
    int dq  = tid & 15;          // dim group (4 dims)
    int pi  = tid >> 4;          // 0..15 (Pt compute row)
    int pj0 = tid & 15;          // Pt compute col base

    float accV[16], accC[16];
    #pragma unroll
    for (int t = 0; t < 16; t++) { accV[t] = 0.f; accC[t] = 0.f; }

    for (int jt = 0; jt < LL/JT; jt++) {
        // ---- V sub-pass ----
        __syncthreads();
        for (int idx = tid; idx < JT*DH; idx += 256) {
            int j = idx >> 6, d = idx & 63;
            Ts[j*68 + d] = g_V[base + (size_t)(jt*JT + j)*EE + d];
        }
        {
            float sa_i = sA[pi], m1_i = m1s[pi], il1_i = il1s[pi];
            #pragma unroll
            for (int jj = 0; jj < 4; jj++) {
                int j = pj0 + jj*16;
                float r = S[pi*1024 + jt*JT + j];
                Pt[j*20 + pi] = __expf(r*sa_i - m1_i) * il1_i;
            }
        }
        __syncthreads();
        #pragma unroll
        for (int jj = 0; jj < 16; jj++) {
            int j = jq*16 + jj;
            float4 p = *(const float4*)&Pt[j*20 + r4u*4];
            float4 v = *(const float4*)&Ts[j*68 + dq*4];
            accV[ 0] += p.x*v.x; accV[ 1] += p.x*v.y; accV[ 2] += p.x*v.z; accV[ 3] += p.x*v.w;
            accV[ 4] += p.y*v.x; accV[ 5] += p.y*v.y; accV[ 6] += p.y*v.z; accV[ 7] += p.y*v.w;
            accV[ 8] += p.z*v.x; accV[ 9] += p.z*v.y; accV[10] += p.z*v.z; accV[11] += p.z*v.w;
            accV[12] += p.w*v.x; accV[13] += p.w*v.y; accV[14] += p.w*v.z; accV[15] += p.w*v.w;
        }

        // ---- Cp sub-pass ----
        __syncthreads();
        for (int idx = tid; idx < JT*DH; idx += 256) {
            int j = idx >> 6, d = idx & 63;
            Ts[j*68 + d] = g_Cp[base + (size_t)(jt*JT + j)*EE + d];
        }
        {
            float w_i = w2[pi], m2_i = m2s[pi], il2_i = il2s[pi];
            #pragma unroll
            for (int jj = 0; jj < 4; jj++) {
                int j = pj0 + jj*16;
                float r = S[pi*1024 + jt*JT + j];
                Pt[j*20 + pi] = __expf(r*cqs[jt*JT + j]*w_i - m2_i) * il2_i;
            }
        }
        __syncthreads();
        #pragma unroll
        for (int jj = 0; jj < 16; jj++) {
            int j = jq*16 + jj;
            float4 p = *(const float4*)&Pt[j*20 + r4u*4];
            float4 v = *(const float4*)&Ts[j*68 + dq*4];
            accC[ 0] += p.x*v.x; accC[ 1] += p.x*v.y; accC[ 2] += p.x*v.z; accC[ 3] += p.x*v.w;
            accC[ 4] += p.y*v.x; accC[ 5] += p.y*v.y; accC[ 6] += p.y*v.z; accC[ 7] += p.y*v.w;
            accC[ 8] += p.z*v.x; accC[ 9] += p.z*v.y; accC[10] += p.z*v.z; accC[11] += p.z*v.w;
            accC[12] += p.w*v.x; accC[13] += p.w*v.y; accC[14] += p.w*v.z; accC[15] += p.w*v.w;
        }
    }

    // Reduction across the 4 j-split groups (reuse S region — raw scores done)
    __syncthreads();
    float* redV = S;                 // [4][16][68]
    float* redC = S + 4*16*68;       // [4][16][68]
    #pragma unroll
    for (int ri = 0; ri < 4; ri++) {
        int row = r4u*4 + ri;
        *(float4*)&redV[(jq*16 + row)*68 + dq*4] =
            make_float4(accV[ri*4+0], accV[ri*4+1], accV[ri*4+2], accV[ri*4+3]);
        *(float4*)&redC[(jq*16 + row)*68 + dq*4] =
            make_float4(accC[ri*4+0], accC[ri*4+1], accC[ri*4+2], accC[ri*4+3]);
    }
    __syncthreads();
    {
        int i = tid >> 4, d4 = (tid & 15)*4;
        float4 o = make_float4(0.f, 0.f, 0.f, 0.f);
        #pragma unroll
        for (int q = 0; q < 4; q++) {
            float4 a = *(const float4*)&redV[(q*16 + i)*68 + d4];
            float4 c = *(const float4*)&redC[(q*16 + i)*68 + d4];
            o.x += a.x + c.x; o.y += a.y + c.y; o.z += a.z + c.z; o.w += a.w + c.w;
        }
        *(float4*)&g_vals[((size_t)b*SS + 1 + i0 + i)*EE + h*DH + d4] = o;
    }
}

// ---------------- launch ----------------------------------------------------
extern "C" void kernel_launch(void* const* d_in, const int* in_sizes, int n_in,
                              void* d_out, int out_size)
{
    const float* x  = (const float*)d_in[0];
    const float* Wq = (const float*)d_in[1];
    const float* bq = (const float*)d_in[2];
    const float* Wk = (const float*)d_in[3];
    const float* bk = (const float*)d_in[4];
    const float* Wv = (const float*)d_in[5];
    const float* bv = (const float*)d_in[6];
    const float* Wo = (const float*)d_in[7];
    const float* bo = (const float*)d_in[8];
    const float* Wc = (const float*)d_in[9];
    const float* bc = (const float*)d_in[10];

    float* out  = (float*)d_out;                      // (B,1025,E)
    float* attn = out + (size_t)Bb*SS*EE;             // (B,H,1024,1024)

    float* dVals;
    cudaGetSymbolAddress((void**)&dVals, g_vals);

    const int SMEM_BYTES = (MT*1024 + 5632 + 1024 + 6*MT) * sizeof(float);
    cudaFuncSetAttribute(attn_kernel, cudaFuncAttributeMaxDynamicSharedMemorySize, SMEM_BYTES);

    proj4_tf32<<<dim3(32, 64), 256>>>(x, Wq, bq, Wk, bk, Wv, bv, Wc, bc);

    cls_proj_kernel<<<16, 256>>>(x, Wq, bq);
    cn2_kernel<<<1, 64>>>();
    qn2_kernel<<<256, 256>>>();
    cq_kernel<<<256, 256>>>();
    o2c_kernel<<<dim3(HH, Bb), 256>>>();

    attn_kernel<<<dim3(LL/MT, HH, Bb), 256, SMEM_BYTES>>>(attn);

    dim3 gOut((Bb*SS + 63) / 64, 16);
    sgemm_nt<<<gOut, 256>>>(dVals, 1, Wo, bo, out, Bb*SS);
}

// round 5
// speedup vs baseline: 2.8403x; 1.7759x over previous
#include <cuda_runtime.h>
#include <math.h>

#define Bb 4
#define SS 1025
#define LL 1024
#define EE 1024
#define HH 16
#define DH 64
#define EPSV 1e-5f

#define MT2 32          // attention rows per block
#define SD  1028        // S row stride (words), conflict-free
#define PSD 132         // P tile row stride
#define TSD 68          // K tile row stride ([j][d])
#define VSD 133         // V^T tile row stride ([d][j])

// ---------------- scratch (static device globals; no allocs allowed) -------
__device__ float g_Q [Bb*LL*EE];
__device__ float g_K [Bb*LL*EE];
__device__ float g_V [Bb*LL*EE];
__device__ float g_Cp[Bb*LL*EE];
__device__ float g_vals[Bb*SS*EE];
__device__ float g_qn2[Bb*LL*HH];
__device__ float g_c  [Bb*EE];
__device__ float g_cn2[Bb*HH];
__device__ float g_cq [Bb*HH*LL];

// ---------------- tf32 helpers ---------------------------------------------
__device__ __forceinline__ unsigned f2tf32(float x) {
    unsigned r;
    asm("cvt.rna.tf32.f32 %0, %1;" : "=r"(r) : "f"(x));
    return r;
}

__device__ __forceinline__ void mma_tf32(float& c0, float& c1, float& c2, float& c3,
                                         unsigned a0, unsigned a1, unsigned a2, unsigned a3,
                                         unsigned b0, unsigned b1)
{
    asm volatile("mma.sync.aligned.m16n8k8.row.col.f32.tf32.tf32.f32 "
                 "{%0,%1,%2,%3}, {%4,%5,%6,%7}, {%8,%9}, {%0,%1,%2,%3};"
                 : "+f"(c0), "+f"(c1), "+f"(c2), "+f"(c3)
                 : "r"(a0), "r"(a1), "r"(a2), "r"(a3), "r"(b0), "r"(b1));
}

// ---------------- fused Q/K/V/Cp projections (tf32 tensor core) ------------
__global__ __launch_bounds__(256) void proj4_tf32(
    const float* __restrict__ x,
    const float* __restrict__ Wq, const float* __restrict__ bq,
    const float* __restrict__ Wk, const float* __restrict__ bk,
    const float* __restrict__ Wv, const float* __restrict__ bv,
    const float* __restrict__ Wc, const float* __restrict__ bc)
{
    __shared__ unsigned As[128][36];
    __shared__ unsigned Bs[64][36];

    int tid = threadIdx.x;
    int m0 = blockIdx.x * 128;
    int y  = blockIdx.y;
    int which = y >> 4;
    int n0 = (y & 15) * 64;

    const float* W; const float* bias; float* dst;
    switch (which) {
        case 0:  W = Wq; bias = bq; dst = g_Q;  break;
        case 1:  W = Wk; bias = bk; dst = g_K;  break;
        case 2:  W = Wv; bias = bv; dst = g_V;  break;
        default: W = Wc; bias = bc; dst = g_Cp; break;
    }

    int warp = tid >> 5, lane = tid & 31;
    int wm = warp >> 1, wn = warp & 1;
    int gid = lane >> 2, tig = lane & 3;

    float acc[2][4][4];
    #pragma unroll
    for (int mi = 0; mi < 2; mi++)
        #pragma unroll
        for (int ni = 0; ni < 4; ni++)
            #pragma unroll
            for (int c = 0; c < 4; c++) acc[mi][ni][c] = 0.f;

    int lr = tid >> 3;
    int lk = (tid & 7) * 4;

    for (int k0 = 0; k0 < EE; k0 += 32) {
        #pragma unroll
        for (int r = 0; r < 4; r++) {
            int m = m0 + lr + r * 32;
            int b = m >> 10, t = m & 1023;
            float4 v = *(const float4*)(x + (size_t)(b * SS + t + 1) * EE + k0 + lk);
            As[lr + r * 32][lk + 0] = f2tf32(v.x);
            As[lr + r * 32][lk + 1] = f2tf32(v.y);
            As[lr + r * 32][lk + 2] = f2tf32(v.z);
            As[lr + r * 32][lk + 3] = f2tf32(v.w);
        }
        #pragma unroll
        for (int r = 0; r < 2; r++) {
            float4 v = *(const float4*)(W + (size_t)(n0 + lr + r * 32) * EE + k0 + lk);
            Bs[lr + r * 32][lk + 0] = f2tf32(v.x);
            Bs[lr + r * 32][lk + 1] = f2tf32(v.y);
            Bs[lr + r * 32][lk + 2] = f2tf32(v.z);
            Bs[lr + r * 32][lk + 3] = f2tf32(v.w);
        }
        __syncthreads();

        #pragma unroll
        for (int kk = 0; kk < 32; kk += 8) {
            unsigned a[2][4], bfr[4][2];
            #pragma unroll
            for (int mi = 0; mi < 2; mi++) {
                int mb = wm * 32 + mi * 16;
                a[mi][0] = As[mb + gid    ][kk + tig    ];
                a[mi][1] = As[mb + gid + 8][kk + tig    ];
                a[mi][2] = As[mb + gid    ][kk + tig + 4];
                a[mi][3] = As[mb + gid + 8][kk + tig + 4];
            }
            #pragma unroll
            for (int ni = 0; ni < 4; ni++) {
                int nb = wn * 32 + ni * 8;
                bfr[ni][0] = Bs[nb + gid][kk + tig    ];
                bfr[ni][1] = Bs[nb + gid][kk + tig + 4];
            }
            #pragma unroll
            for (int mi = 0; mi < 2; mi++)
                #pragma unroll
                for (int ni = 0; ni < 4; ni++)
                    mma_tf32(acc[mi][ni][0], acc[mi][ni][1], acc[mi][ni][2], acc[mi][ni][3],
                             a[mi][0], a[mi][1], a[mi][2], a[mi][3],
                             bfr[ni][0], bfr[ni][1]);
        }
        __syncthreads();
    }

    #pragma unroll
    for (int mi = 0; mi < 2; mi++) {
        int row1 = m0 + wm * 32 + mi * 16 + gid;
        int row2 = row1 + 8;
        #pragma unroll
        for (int ni = 0; ni < 4; ni++) {
            int col = n0 + wn * 32 + ni * 8 + tig * 2;
            float b0v = bias[col], b1v = bias[col + 1];
            float2 o1 = make_float2(acc[mi][ni][0] + b0v, acc[mi][ni][1] + b1v);
            float2 o2 = make_float2(acc[mi][ni][2] + b0v, acc[mi][ni][3] + b1v);
            *(float2*)(dst + (size_t)row1 * EE + col) = o1;
            *(float2*)(dst + (size_t)row2 * EE + col) = o2;
        }
    }
}

// ---------------- fp32 NT SGEMM (output projection) -------------------------
__global__ void sgemm_nt(const float* __restrict__ A, int amode,
                         const float* __restrict__ W,
                         const float* __restrict__ bias,
                         float* __restrict__ Y, int M)
{
    __shared__ float As[16][68];
    __shared__ float Bs[16][68];
    int tid = threadIdx.x;
    int tx = tid & 15, ty = tid >> 4;
    int m0 = blockIdx.x * 64, n0 = blockIdx.y * 64;

    int lr = tid >> 2;
    int lk = (tid & 3) << 2;

    int m = m0 + lr;
    bool mv = (m < M);
    const float* arow = A;
    if (mv) {
        if (amode == 0) { int b = m >> 10; int t = m & 1023; arow = A + (size_t)(b*SS + t + 1)*EE; }
        else            { arow = A + (size_t)m*EE; }
    }
    const float* wrow = W + (size_t)(n0 + lr)*EE;

    float acc[4][4];
    #pragma unroll
    for (int r = 0; r < 4; r++)
        #pragma unroll
        for (int c = 0; c < 4; c++) acc[r][c] = 0.f;

    for (int k0 = 0; k0 < EE; k0 += 16) {
        float4 av = mv ? *(const float4*)(arow + k0 + lk) : make_float4(0.f,0.f,0.f,0.f);
        float4 wv = *(const float4*)(wrow + k0 + lk);
        As[lk+0][lr] = av.x; As[lk+1][lr] = av.y; As[lk+2][lr] = av.z; As[lk+3][lr] = av.w;
        Bs[lk+0][lr] = wv.x; Bs[lk+1][lr] = wv.y; Bs[lk+2][lr] = wv.z; Bs[lk+3][lr] = wv.w;
        __syncthreads();
        #pragma unroll
        for (int kk = 0; kk < 16; kk++) {
            float4 a  = *(const float4*)&As[kk][ty*4];
            float4 bv = *(const float4*)&Bs[kk][tx*4];
            acc[0][0] += a.x*bv.x; acc[0][1] += a.x*bv.y; acc[0][2] += a.x*bv.z; acc[0][3] += a.x*bv.w;
            acc[1][0] += a.y*bv.x; acc[1][1] += a.y*bv.y; acc[1][2] += a.y*bv.z; acc[1][3] += a.y*bv.w;
            acc[2][0] += a.z*bv.x; acc[2][1] += a.z*bv.y; acc[2][2] += a.z*bv.z; acc[2][3] += a.z*bv.w;
            acc[3][0] += a.w*bv.x; acc[3][1] += a.w*bv.y; acc[3][2] += a.w*bv.z; acc[3][3] += a.w*bv.w;
        }
        __syncthreads();
    }

    float4 bv = *(const float4*)(bias + n0 + tx*4);
    #pragma unroll
    for (int r = 0; r < 4; r++) {
        int mm = m0 + ty*4 + r;
        if (mm < M) {
            float4 o = make_float4(acc[r][0]+bv.x, acc[r][1]+bv.y, acc[r][2]+bv.z, acc[r][3]+bv.w);
            *(float4*)(Y + (size_t)mm*EE + n0 + tx*4) = o;
        }
    }
}

// ---------------- small kernels ---------------------------------------------
__global__ void cls_proj_kernel(const float* __restrict__ x,
                                const float* __restrict__ Wq,
                                const float* __restrict__ bq)
{
    int idx = blockIdx.x * blockDim.x + threadIdx.x;
    int b = idx >> 10, n = idx & 1023;
    const float* xr = x + (size_t)b*SS*EE;
    const float* wr = Wq + (size_t)n*EE;
    float s = 0.f;
    for (int k = 0; k < EE; k += 4) {
        float4 xv = *(const float4*)(xr + k);
        float4 wv = *(const float4*)(wr + k);
        s += xv.x*wv.x + xv.y*wv.y + xv.z*wv.z + xv.w*wv.w;
    }
    g_c[idx] = s + bq[n];
}

__global__ void cn2_kernel()
{
    int t = threadIdx.x;
    const float* c = g_c + (t >> 4)*EE + (t & 15)*DH;
    float s = 0.f;
    #pragma unroll
    for (int d = 0; d < DH; d++) s += c[d]*c[d];
    g_cn2[t] = fmaxf(s, EPSV);
}

__global__ void qn2_kernel()
{
    int idx = blockIdx.x * blockDim.x + threadIdx.x;
    int bt = idx >> 4, h = idx & 15;
    const float* q = g_Q + (size_t)bt*EE + h*DH;
    float s = 0.f;
    #pragma unroll
    for (int d = 0; d < DH; d += 4) {
        float4 v = *(const float4*)(q + d);
        s += v.x*v.x + v.y*v.y + v.z*v.z + v.w*v.w;
    }
    g_qn2[idx] = fmaxf(s, EPSV);
}

__global__ void cq_kernel()
{
    int idx = blockIdx.x * blockDim.x + threadIdx.x;
    int bh = idx >> 10, j = idx & 1023;
    int b = bh >> 4, h = bh & 15;
    const float* c = g_c + (size_t)b*EE + h*DH;
    const float* q = g_Q + (size_t)(b*LL + j)*EE + h*DH;
    float s = 0.f;
    #pragma unroll
    for (int d = 0; d < DH; d += 4) {
        float4 cv = *(const float4*)(c + d);
        float4 qv = *(const float4*)(q + d);
        s += cv.x*qv.x + cv.y*qv.y + cv.z*qv.z + cv.w*qv.w;
    }
    g_cq[idx] = s;
}

__global__ void o2c_kernel()
{
    __shared__ float cs[64];
    __shared__ float ck[1024];
    __shared__ float red[256];
    int h = blockIdx.x, b = blockIdx.y;
    int bh = b*HH + h;
    int tid = threadIdx.x;

    if (tid < 64) cs[tid] = g_c[(size_t)b*EE + h*DH + tid];
    __syncthreads();

    float scale = rsqrtf(64.f * g_cn2[bh]);
    for (int j = tid; j < 1024; j += 256) {
        const float* kr = g_K + (size_t)(b*LL + j)*EE + h*DH;
        float s = 0.f;
        #pragma unroll
        for (int d = 0; d < DH; d += 4) {
            float4 cv = *(const float4*)(cs + d);
            float4 kv = *(const float4*)(kr + d);
            s += cv.x*kv.x + cv.y*kv.y + cv.z*kv.z + cv.w*kv.w;
        }
        ck[j] = s * scale;
    }
    __syncthreads();

    float m = -1e30f;
    for (int j = tid; j < 1024; j += 256) m = fmaxf(m, ck[j]);
    red[tid] = m; __syncthreads();
    for (int s = 128; s > 0; s >>= 1) { if (tid < s) red[tid] = fmaxf(red[tid], red[tid+s]); __syncthreads(); }
    m = red[0]; __syncthreads();

    float l = 0.f;
    for (int j = tid; j < 1024; j += 256) { float e = __expf(ck[j] - m); ck[j] = e; l += e; }
    red[tid] = l; __syncthreads();
    for (int s = 128; s > 0; s >>= 1) { if (tid < s) red[tid] += red[tid+s]; __syncthreads(); }
    l = red[0]; __syncthreads();
    float invl = 1.f / l;

    int d = tid & 63, part = tid >> 6;
    float s = 0.f;
    for (int j = part; j < 1024; j += 4)
        s += ck[j] * g_V[(size_t)(b*LL + j)*EE + h*DH + d];
    red[tid] = s; __syncthreads();
    if (part == 0) {
        float tot = red[d] + red[64+d] + red[128+d] + red[192+d];
        g_vals[(size_t)b*SS*EE + h*DH + d] = tot * invl;
    }
}

// ---------------- fused attention core (tf32 mma) ---------------------------
__global__ __launch_bounds__(512) void attn_mma(float* __restrict__ attn_out)
{
    extern __shared__ float sm[];
    float*    S    = sm;                              // [32][SD]
    unsigned* Tile = (unsigned*)(S + MT2*SD);          // [128][68] / [64][133]
    unsigned* UQ   = Tile + 128*TSD;                   // Qs [32][68] | Ps [32][132]
    float*    cqs  = (float*)(UQ + MT2*PSD);           // 1024
    float*    sA   = cqs + 1024;                       // 32 each
    float*    w2   = sA + MT2;
    float*    m1s  = w2 + MT2;
    float*    il1s = m1s + MT2;
    float*    m2s  = il1s + MT2;
    float*    il2s = m2s + MT2;

    int tid = threadIdx.x;
    int b = blockIdx.z, h = blockIdx.y, i0 = blockIdx.x * MT2;
    int bh = b*HH + h;
    size_t base = (size_t)b*LL*EE + h*DH;

    int warp = tid >> 5, lane = tid & 31;
    int gid = lane >> 2, tig = lane & 3;

    // ---- load Q tile (tf32) + cqs + per-row scales ----
    {
        int r = tid >> 4, d = (tid & 15) * 4;
        float4 v = *(const float4*)(g_Q + base + (size_t)(i0 + r) * EE + d);
        unsigned* q = UQ + r * TSD + d;
        q[0] = f2tf32(v.x); q[1] = f2tf32(v.y); q[2] = f2tf32(v.z); q[3] = f2tf32(v.w);
    }
    for (int idx = tid; idx < 1024; idx += 512)
        cqs[idx] = g_cq[(size_t)bh*LL + idx];
    if (tid < MT2) {
        float qn = g_qn2[(size_t)(b*LL + i0 + tid)*HH + h];
        float s = rsqrtf(64.f * qn);
        sA[tid] = s;
        w2[tid] = s * rsqrtf(qn * g_cn2[bh]);
    }
    __syncthreads();

    // ---- Phase 1: S = Q @ K^T (tf32 mma), jt tiles of 128 cols ----
    {
        int wm = warp & 1;          // m half
        int wn = warp >> 1;         // n section (16 cols)
        int mb = wm * 16;
        // preload Q fragments (8 k-chunks)
        unsigned aQ[8][4];
        #pragma unroll
        for (int kc = 0; kc < 8; kc++) {
            int kk = kc * 8;
            aQ[kc][0] = UQ[(mb + gid    )*TSD + kk + tig    ];
            aQ[kc][1] = UQ[(mb + gid + 8)*TSD + kk + tig    ];
            aQ[kc][2] = UQ[(mb + gid    )*TSD + kk + tig + 4];
            aQ[kc][3] = UQ[(mb + gid + 8)*TSD + kk + tig + 4];
        }
        for (int jt = 0; jt < 8; jt++) {
            // load K tile 128x64 -> tf32 [j][d]
            {
                int r = tid >> 2, d = (tid & 3) * 16;
                const float* src = g_K + base + (size_t)(jt*128 + r)*EE + d;
                unsigned* dst = Tile + r*TSD + d;
                #pragma unroll
                for (int c = 0; c < 4; c++) {
                    float4 v = *(const float4*)(src + c*4);
                    *(uint4*)(dst + c*4) = make_uint4(f2tf32(v.x), f2tf32(v.y), f2tf32(v.z), f2tf32(v.w));
                }
            }
            __syncthreads();
            float acc[2][4];
            #pragma unroll
            for (int nc = 0; nc < 2; nc++)
                #pragma unroll
                for (int c = 0; c < 4; c++) acc[nc][c] = 0.f;
            #pragma unroll
            for (int kc = 0; kc < 8; kc++) {
                int kk = kc * 8;
                #pragma unroll
                for (int nc = 0; nc < 2; nc++) {
                    int nb = wn*16 + nc*8;
                    unsigned b0 = Tile[(nb + gid)*TSD + kk + tig    ];
                    unsigned b1 = Tile[(nb + gid)*TSD + kk + tig + 4];
                    mma_tf32(acc[nc][0], acc[nc][1], acc[nc][2], acc[nc][3],
                             aQ[kc][0], aQ[kc][1], aQ[kc][2], aQ[kc][3], b0, b1);
                }
            }
            #pragma unroll
            for (int nc = 0; nc < 2; nc++) {
                int col = jt*128 + wn*16 + nc*8 + tig*2;
                *(float2*)&S[(mb + gid    )*SD + col] = make_float2(acc[nc][0], acc[nc][1]);
                *(float2*)&S[(mb + gid + 8)*SD + col] = make_float2(acc[nc][2], acc[nc][3]);
            }
            __syncthreads();
        }
    }

    // ---- Phase 2: dual softmax stats (no attn write) ----
    for (int rr = 0; rr < 2; rr++) {
        int i = warp*2 + rr;
        float sa = sA[i], ww = w2[i];
        const float* Sr = &S[i*SD];
        float m1 = -1e30f, mm2 = -1e30f;
        #pragma unroll
        for (int it = 0; it < 8; it++) {
            int j = lane*4 + it*128;
            float4 s4 = *(const float4*)&Sr[j];
            float4 c4 = *(const float4*)&cqs[j];
            m1  = fmaxf(m1,  fmaxf(fmaxf(s4.x*sa,  s4.y*sa),  fmaxf(s4.z*sa,  s4.w*sa)));
            mm2 = fmaxf(mm2, fmaxf(fmaxf(s4.x*c4.x, s4.y*c4.y), fmaxf(s4.z*c4.z, s4.w*c4.w)));
        }
        #pragma unroll
        for (int o = 16; o > 0; o >>= 1) {
            m1  = fmaxf(m1,  __shfl_xor_sync(0xffffffffu, m1,  o));
            mm2 = fmaxf(mm2, __shfl_xor_sync(0xffffffffu, mm2, o));
        }
        float m2 = mm2 * ww;
        float l1 = 0.f, l2 = 0.f;
        #pragma unroll
        for (int it = 0; it < 8; it++) {
            int j = lane*4 + it*128;
            float4 s4 = *(const float4*)&Sr[j];
            float4 c4 = *(const float4*)&cqs[j];
            l1 += __expf(s4.x*sa - m1) + __expf(s4.y*sa - m1)
                + __expf(s4.z*sa - m1) + __expf(s4.w*sa - m1);
            l2 += __expf(s4.x*c4.x*ww - m2) + __expf(s4.y*c4.y*ww - m2)
                + __expf(s4.z*c4.z*ww - m2) + __expf(s4.w*c4.w*ww - m2);
        }
        #pragma unroll
        for (int o = 16; o > 0; o >>= 1) {
            l1 += __shfl_xor_sync(0xffffffffu, l1, o);
            l2 += __shfl_xor_sync(0xffffffffu, l2, o);
        }
        if (lane == 0) { m1s[i] = m1; il1s[i] = 1.f/l1; m2s[i] = m2; il2s[i] = 1.f/l2; }
    }
    __syncthreads();

    // ---- Phase 3: O = P1 @ V + P2 @ Cp (tf32 mma), attn written during P1 staging
    unsigned* Ps = UQ;                 // [32][132]
    int mb3 = (warp & 1) * 16;
    int nb3 = (warp >> 1) * 8;
    int srow = tid >> 4;               // staging row 0..31
    int scol = (tid & 15) * 8;         // staging col base
    float sa_s  = sA[srow],  m1_s = m1s[srow], il1_s = il1s[srow];
    float w2_s  = w2[srow],  m2_s = m2s[srow], il2_s = il2s[srow];
    int dcol = tid & 63;               // V^T load: d index
    int jrow0 = tid >> 6;              // V^T load: j offset 0..7

    float accV[4] = {0.f,0.f,0.f,0.f};
    float accC[4] = {0.f,0.f,0.f,0.f};

    for (int src = 0; src < 2; src++) {
        const float* gsrc = src ? g_Cp : g_V;
        float* accp = src ? accC : accV;
        for (int jt = 0; jt < 8; jt++) {
            __syncthreads();
            // load V/Cp tile transposed: Tile_t[d][j] (tf32), d-major
            #pragma unroll
            for (int it = 0; it < 16; it++) {
                int j = it*8 + jrow0;
                float v = gsrc[base + (size_t)(jt*128 + j)*EE + dcol];
                Tile[dcol*VSD + j] = f2tf32(v);
            }
            // stage P tile [32][128] (tf32) ; write attn for src==0
            {
                const float* Sr = &S[srow*SD + jt*128 + scol];
                float pbuf[8];
                if (src == 0) {
                    #pragma unroll
                    for (int c = 0; c < 8; c++)
                        pbuf[c] = __expf(Sr[c]*sa_s - m1_s) * il1_s;
                    float* arow = attn_out + ((size_t)bh*LL + i0 + srow)*LL + jt*128 + scol;
                    *(float4*)(arow)     = make_float4(pbuf[0], pbuf[1], pbuf[2], pbuf[3]);
                    *(float4*)(arow + 4) = make_float4(pbuf[4], pbuf[5], pbuf[6], pbuf[7]);
                } else {
                    const float* cr = &cqs[jt*128 + scol];
                    #pragma unroll
                    for (int c = 0; c < 8; c++)
                        pbuf[c] = __expf(Sr[c]*cr[c]*w2_s - m2_s) * il2_s;
                }
                unsigned* pd = Ps + srow*PSD + scol;
                *(uint4*)(pd)     = make_uint4(f2tf32(pbuf[0]), f2tf32(pbuf[1]), f2tf32(pbuf[2]), f2tf32(pbuf[3]));
                *(uint4*)(pd + 4) = make_uint4(f2tf32(pbuf[4]), f2tf32(pbuf[5]), f2tf32(pbuf[6]), f2tf32(pbuf[7]));
            }
            __syncthreads();
            // mma: warp output tile 16x8, K = 128
            #pragma unroll
            for (int kc = 0; kc < 16; kc++) {
                int kk = kc * 8;
                unsigned a0 = Ps[(mb3 + gid    )*PSD + kk + tig    ];
                unsigned a1 = Ps[(mb3 + gid + 8)*PSD + kk + tig    ];
                unsigned a2 = Ps[(mb3 + gid    )*PSD + kk + tig + 4];
                unsigned a3 = Ps[(mb3 + gid + 8)*PSD + kk + tig + 4];
                unsigned b0 = Tile[(nb3 + gid)*VSD + kk + tig    ];
                unsigned b1 = Tile[(nb3 + gid)*VSD + kk + tig + 4];
                mma_tf32(accp[0], accp[1], accp[2], accp[3], a0, a1, a2, a3, b0, b1);
            }
        }
    }

    // ---- epilogue: vals rows ----
    {
        int row1 = i0 + mb3 + gid;
        int row2 = row1 + 8;
        int col = h*DH + nb3 + tig*2;
        *(float2*)&g_vals[((size_t)b*SS + 1 + row1)*EE + col] =
            make_float2(accV[0] + accC[0], accV[1] + accC[1]);
        *(float2*)&g_vals[((size_t)b*SS + 1 + row2)*EE + col] =
            make_float2(accV[2] + accC[2], accV[3] + accC[3]);
    }
}

// ---------------- launch ----------------------------------------------------
extern "C" void kernel_launch(void* const* d_in, const int* in_sizes, int n_in,
                              void* d_out, int out_size)
{
    const float* x  = (const float*)d_in[0];
    const float* Wq = (const float*)d_in[1];
    const float* bq = (const float*)d_in[2];
    const float* Wk = (const float*)d_in[3];
    const float* bk = (const float*)d_in[4];
    const float* Wv = (const float*)d_in[5];
    const float* bv = (const float*)d_in[6];
    const float* Wo = (const float*)d_in[7];
    const float* bo = (const float*)d_in[8];
    const float* Wc = (const float*)d_in[9];
    const float* bc = (const float*)d_in[10];

    float* out  = (float*)d_out;                      // (B,1025,E)
    float* attn = out + (size_t)Bb*SS*EE;             // (B,H,1024,1024)

    float* dVals;
    cudaGetSymbolAddress((void**)&dVals, g_vals);

    const int SMEM_BYTES = (MT2*SD + 128*TSD + MT2*PSD + 1024 + 6*MT2) * sizeof(float);
    cudaFuncSetAttribute(attn_mma, cudaFuncAttributeMaxDynamicSharedMemorySize, SMEM_BYTES);

    proj4_tf32<<<dim3(32, 64), 256>>>(x, Wq, bq, Wk, bk, Wv, bv, Wc, bc);

    cls_proj_kernel<<<16, 256>>>(x, Wq, bq);
    cn2_kernel<<<1, 64>>>();
    qn2_kernel<<<256, 256>>>();
    cq_kernel<<<256, 256>>>();
    o2c_kernel<<<dim3(HH, Bb), 256>>>();

    attn_mma<<<dim3(LL/MT2, HH, Bb), 512, SMEM_BYTES>>>(attn);

    dim3 gOut((Bb*SS + 63) / 64, 16);
    sgemm_nt<<<gOut, 256>>>(dVals, 1, Wo, bo, out, Bb*SS);
}

// round 7
// speedup vs baseline: 3.7359x; 1.3153x over previous
#include <cuda_runtime.h>
#include <math.h>

#define Bb 4
#define SS 1025
#define LL 1024
#define EE 1024
#define HH 16
#define DH 64
#define EPSV 1e-5f

#define MT2 32          // attention rows per block
#define SD  1028        // S row stride (words)
#define KSD 68          // K tile stride (phase 1, [j][d])
#define VSD3 68         // Vt/Ct tile stride (phase 3, [d][j])
#define PSD3 68         // P tile stride (phase 3, [i][j])

// ---------------- scratch (static device globals; no allocs allowed) -------
__device__ float g_Q [Bb*LL*EE];
__device__ float g_K [Bb*LL*EE];
__device__ float g_V [Bb*LL*EE];
__device__ float g_Cp[Bb*LL*EE];
__device__ float g_vals[Bb*SS*EE];
__device__ float g_qn2[Bb*LL*HH];
__device__ float g_c  [Bb*EE];
__device__ float g_cn2[Bb*HH];
__device__ float g_cq [Bb*HH*LL];

// ---------------- tf32 helpers ---------------------------------------------
__device__ __forceinline__ unsigned f2tf32(float x) {
    unsigned r;
    asm("cvt.rna.tf32.f32 %0, %1;" : "=r"(r) : "f"(x));
    return r;
}

__device__ __forceinline__ void mma_tf32(float& c0, float& c1, float& c2, float& c3,
                                         unsigned a0, unsigned a1, unsigned a2, unsigned a3,
                                         unsigned b0, unsigned b1)
{
    asm volatile("mma.sync.aligned.m16n8k8.row.col.f32.tf32.tf32.f32 "
                 "{%0,%1,%2,%3}, {%4,%5,%6,%7}, {%8,%9}, {%0,%1,%2,%3};"
                 : "+f"(c0), "+f"(c1), "+f"(c2), "+f"(c3)
                 : "r"(a0), "r"(a1), "r"(a2), "r"(a3), "r"(b0), "r"(b1));
}

// ---------------- fused Q/K/V/Cp projections (tf32 tensor core) ------------
__global__ __launch_bounds__(256) void proj4_tf32(
    const float* __restrict__ x,
    const float* __restrict__ Wq, const float* __restrict__ bq,
    const float* __restrict__ Wk, const float* __restrict__ bk,
    const float* __restrict__ Wv, const float* __restrict__ bv,
    const float* __restrict__ Wc, const float* __restrict__ bc)
{
    __shared__ unsigned As[128][36];
    __shared__ unsigned Bs[64][36];

    int tid = threadIdx.x;
    int m0 = blockIdx.x * 128;
    int y  = blockIdx.y;
    int which = y >> 4;
    int n0 = (y & 15) * 64;

    const float* W; const float* bias; float* dst;
    switch (which) {
        case 0:  W = Wq; bias = bq; dst = g_Q;  break;
        case 1:  W = Wk; bias = bk; dst = g_K;  break;
        case 2:  W = Wv; bias = bv; dst = g_V;  break;
        default: W = Wc; bias = bc; dst = g_Cp; break;
    }

    int warp = tid >> 5, lane = tid & 31;
    int wm = warp >> 1, wn = warp & 1;
    int gid = lane >> 2, tig = lane & 3;

    float acc[2][4][4];
    #pragma unroll
    for (int mi = 0; mi < 2; mi++)
        #pragma unroll
        for (int ni = 0; ni < 4; ni++)
            #pragma unroll
            for (int c = 0; c < 4; c++) acc[mi][ni][c] = 0.f;

    int lr = tid >> 3;
    int lk = (tid & 7) * 4;

    for (int k0 = 0; k0 < EE; k0 += 32) {
        #pragma unroll
        for (int r = 0; r < 4; r++) {
            int m = m0 + lr + r * 32;
            int b = m >> 10, t = m & 1023;
            float4 v = *(const float4*)(x + (size_t)(b * SS + t + 1) * EE + k0 + lk);
            As[lr + r * 32][lk + 0] = f2tf32(v.x);
            As[lr + r * 32][lk + 1] = f2tf32(v.y);
            As[lr + r * 32][lk + 2] = f2tf32(v.z);
            As[lr + r * 32][lk + 3] = f2tf32(v.w);
        }
        #pragma unroll
        for (int r = 0; r < 2; r++) {
            float4 v = *(const float4*)(W + (size_t)(n0 + lr + r * 32) * EE + k0 + lk);
            Bs[lr + r * 32][lk + 0] = f2tf32(v.x);
            Bs[lr + r * 32][lk + 1] = f2tf32(v.y);
            Bs[lr + r * 32][lk + 2] = f2tf32(v.z);
            Bs[lr + r * 32][lk + 3] = f2tf32(v.w);
        }
        __syncthreads();

        #pragma unroll
        for (int kk = 0; kk < 32; kk += 8) {
            unsigned a[2][4], bfr[4][2];
            #pragma unroll
            for (int mi = 0; mi < 2; mi++) {
                int mb = wm * 32 + mi * 16;
                a[mi][0] = As[mb + gid    ][kk + tig    ];
                a[mi][1] = As[mb + gid + 8][kk + tig    ];
                a[mi][2] = As[mb + gid    ][kk + tig + 4];
                a[mi][3] = As[mb + gid + 8][kk + tig + 4];
            }
            #pragma unroll
            for (int ni = 0; ni < 4; ni++) {
                int nb = wn * 32 + ni * 8;
                bfr[ni][0] = Bs[nb + gid][kk + tig    ];
                bfr[ni][1] = Bs[nb + gid][kk + tig + 4];
            }
            #pragma unroll
            for (int mi = 0; mi < 2; mi++)
                #pragma unroll
                for (int ni = 0; ni < 4; ni++)
                    mma_tf32(acc[mi][ni][0], acc[mi][ni][1], acc[mi][ni][2], acc[mi][ni][3],
                             a[mi][0], a[mi][1], a[mi][2], a[mi][3],
                             bfr[ni][0], bfr[ni][1]);
        }
        __syncthreads();
    }

    #pragma unroll
    for (int mi = 0; mi < 2; mi++) {
        int row1 = m0 + wm * 32 + mi * 16 + gid;
        int row2 = row1 + 8;
        #pragma unroll
        for (int ni = 0; ni < 4; ni++) {
            int col = n0 + wn * 32 + ni * 8 + tig * 2;
            float b0v = bias[col], b1v = bias[col + 1];
            float2 o1 = make_float2(acc[mi][ni][0] + b0v, acc[mi][ni][1] + b1v);
            float2 o2 = make_float2(acc[mi][ni][2] + b0v, acc[mi][ni][3] + b1v);
            *(float2*)(dst + (size_t)row1 * EE + col) = o1;
            *(float2*)(dst + (size_t)row2 * EE + col) = o2;
        }
    }
}

// ---------------- tf32 output projection: out = vals @ Wo^T + bo ------------
// M = 4100 rows (with bounds), grid (33, 16)
__global__ __launch_bounds__(256) void sgemmo_tf32(
    const float* __restrict__ A,      // g_vals [4100][1024]
    const float* __restrict__ W,      // Wo
    const float* __restrict__ bias,   // bo
    float* __restrict__ Y)            // out [4100][1024]
{
    const int M = Bb * SS;   // 4100
    __shared__ unsigned As[128][36];
    __shared__ unsigned Bs[64][36];

    int tid = threadIdx.x;
    int m0 = blockIdx.x * 128;
    int n0 = blockIdx.y * 64;

    int warp = tid >> 5, lane = tid & 31;
    int wm = warp >> 1, wn = warp & 1;
    int gid = lane >> 2, tig = lane & 3;

    float acc[2][4][4];
    #pragma unroll
    for (int mi = 0; mi < 2; mi++)
        #pragma unroll
        for (int ni = 0; ni < 4; ni++)
            #pragma unroll
            for (int c = 0; c < 4; c++) acc[mi][ni][c] = 0.f;

    int lr = tid >> 3;
    int lk = (tid & 7) * 4;

    for (int k0 = 0; k0 < EE; k0 += 32) {
        #pragma unroll
        for (int r = 0; r < 4; r++) {
            int m = m0 + lr + r * 32;
            float4 v = (m < M) ? *(const float4*)(A + (size_t)m * EE + k0 + lk)
                               : make_float4(0.f, 0.f, 0.f, 0.f);
            As[lr + r * 32][lk + 0] = f2tf32(v.x);
            As[lr + r * 32][lk + 1] = f2tf32(v.y);
            As[lr + r * 32][lk + 2] = f2tf32(v.z);
            As[lr + r * 32][lk + 3] = f2tf32(v.w);
        }
        #pragma unroll
        for (int r = 0; r < 2; r++) {
            float4 v = *(const float4*)(W + (size_t)(n0 + lr + r * 32) * EE + k0 + lk);
            Bs[lr + r * 32][lk + 0] = f2tf32(v.x);
            Bs[lr + r * 32][lk + 1] = f2tf32(v.y);
            Bs[lr + r * 32][lk + 2] = f2tf32(v.z);
            Bs[lr + r * 32][lk + 3] = f2tf32(v.w);
        }
        __syncthreads();

        #pragma unroll
        for (int kk = 0; kk < 32; kk += 8) {
            unsigned a[2][4], bfr[4][2];
            #pragma unroll
            for (int mi = 0; mi < 2; mi++) {
                int mb = wm * 32 + mi * 16;
                a[mi][0] = As[mb + gid    ][kk + tig    ];
                a[mi][1] = As[mb + gid + 8][kk + tig    ];
                a[mi][2] = As[mb + gid    ][kk + tig + 4];
                a[mi][3] = As[mb + gid + 8][kk + tig + 4];
            }
            #pragma unroll
            for (int ni = 0; ni < 4; ni++) {
                int nb = wn * 32 + ni * 8;
                bfr[ni][0] = Bs[nb + gid][kk + tig    ];
                bfr[ni][1] = Bs[nb + gid][kk + tig + 4];
            }
            #pragma unroll
            for (int mi = 0; mi < 2; mi++)
                #pragma unroll
                for (int ni = 0; ni < 4; ni++)
                    mma_tf32(acc[mi][ni][0], acc[mi][ni][1], acc[mi][ni][2], acc[mi][ni][3],
                             a[mi][0], a[mi][1], a[mi][2], a[mi][3],
                             bfr[ni][0], bfr[ni][1]);
        }
        __syncthreads();
    }

    #pragma unroll
    for (int mi = 0; mi < 2; mi++) {
        int row1 = m0 + wm * 32 + mi * 16 + gid;
        int row2 = row1 + 8;
        #pragma unroll
        for (int ni = 0; ni < 4; ni++) {
            int col = n0 + wn * 32 + ni * 8 + tig * 2;
            float b0v = bias[col], b1v = bias[col + 1];
            if (row1 < M)
                *(float2*)(Y + (size_t)row1 * EE + col) =
                    make_float2(acc[mi][ni][0] + b0v, acc[mi][ni][1] + b1v);
            if (row2 < M)
                *(float2*)(Y + (size_t)row2 * EE + col) =
                    make_float2(acc[mi][ni][2] + b0v, acc[mi][ni][3] + b1v);
        }
    }
}

// ---------------- small kernels ---------------------------------------------
__global__ void cls_proj_kernel(const float* __restrict__ x,
                                const float* __restrict__ Wq,
                                const float* __restrict__ bq)
{
    int idx = blockIdx.x * blockDim.x + threadIdx.x;
    int b = idx >> 10, n = idx & 1023;
    const float* xr = x + (size_t)b*SS*EE;
    const float* wr = Wq + (size_t)n*EE;
    float s = 0.f;
    for (int k = 0; k < EE; k += 4) {
        float4 xv = *(const float4*)(xr + k);
        float4 wv = *(const float4*)(wr + k);
        s += xv.x*wv.x + xv.y*wv.y + xv.z*wv.z + xv.w*wv.w;
    }
    g_c[idx] = s + bq[n];
}

__global__ void cn2_kernel()
{
    int t = threadIdx.x;
    const float* c = g_c + (t >> 4)*EE + (t & 15)*DH;
    float s = 0.f;
    #pragma unroll
    for (int d = 0; d < DH; d++) s += c[d]*c[d];
    g_cn2[t] = fmaxf(s, EPSV);
}

__global__ void qn2_kernel()
{
    int idx = blockIdx.x * blockDim.x + threadIdx.x;
    int bt = idx >> 4, h = idx & 15;
    const float* q = g_Q + (size_t)bt*EE + h*DH;
    float s = 0.f;
    #pragma unroll
    for (int d = 0; d < DH; d += 4) {
        float4 v = *(const float4*)(q + d);
        s += v.x*v.x + v.y*v.y + v.z*v.z + v.w*v.w;
    }
    g_qn2[idx] = fmaxf(s, EPSV);
}

__global__ void cq_kernel()
{
    int idx = blockIdx.x * blockDim.x + threadIdx.x;
    int bh = idx >> 10, j = idx & 1023;
    int b = bh >> 4, h = bh & 15;
    const float* c = g_c + (size_t)b*EE + h*DH;
    const float* q = g_Q + (size_t)(b*LL + j)*EE + h*DH;
    float s = 0.f;
    #pragma unroll
    for (int d = 0; d < DH; d += 4) {
        float4 cv = *(const float4*)(c + d);
        float4 qv = *(const float4*)(q + d);
        s += cv.x*qv.x + cv.y*qv.y + cv.z*qv.z + cv.w*qv.w;
    }
    g_cq[idx] = s;
}

__global__ void o2c_kernel()
{
    __shared__ float cs[64];
    __shared__ float ck[1024];
    __shared__ float red[256];
    int h = blockIdx.x, b = blockIdx.y;
    int bh = b*HH + h;
    int tid = threadIdx.x;

    if (tid < 64) cs[tid] = g_c[(size_t)b*EE + h*DH + tid];
    __syncthreads();

    float scale = rsqrtf(64.f * g_cn2[bh]);
    for (int j = tid; j < 1024; j += 256) {
        const float* kr = g_K + (size_t)(b*LL + j)*EE + h*DH;
        float s = 0.f;
        #pragma unroll
        for (int d = 0; d < DH; d += 4) {
            float4 cv = *(const float4*)(cs + d);
            float4 kv = *(const float4*)(kr + d);
            s += cv.x*kv.x + cv.y*kv.y + cv.z*kv.z + cv.w*kv.w;
        }
        ck[j] = s * scale;
    }
    __syncthreads();

    float m = -1e30f;
    for (int j = tid; j < 1024; j += 256) m = fmaxf(m, ck[j]);
    red[tid] = m; __syncthreads();
    for (int s = 128; s > 0; s >>= 1) { if (tid < s) red[tid] = fmaxf(red[tid], red[tid+s]); __syncthreads(); }
    m = red[0]; __syncthreads();

    float l = 0.f;
    for (int j = tid; j < 1024; j += 256) { float e = __expf(ck[j] - m); ck[j] = e; l += e; }
    red[tid] = l; __syncthreads();
    for (int s = 128; s > 0; s >>= 1) { if (tid < s) red[tid] += red[tid+s]; __syncthreads(); }
    l = red[0]; __syncthreads();
    float invl = 1.f / l;

    int d = tid & 63, part = tid >> 6;
    float s = 0.f;
    for (int j = part; j < 1024; j += 4)
        s += ck[j] * g_V[(size_t)(b*LL + j)*EE + h*DH + d];
    red[tid] = s; __syncthreads();
    if (part == 0) {
        float tot = red[d] + red[64+d] + red[128+d] + red[192+d];
        g_vals[(size_t)b*SS*EE + h*DH + d] = tot * invl;
    }
}

// ---------------- fused attention core (tf32 mma, warp-split phase 3) -------
__global__ __launch_bounds__(512) void attn_mma(float* __restrict__ attn_out)
{
    extern __shared__ float sm[];
    float*    S    = sm;                               // [32][1028]
    unsigned* Tile = (unsigned*)(S + MT2*SD);          // 8704 w: K[128][68] | Vt[64][68]+Ct[64][68]
    unsigned* Pq   = Tile + 8704;                      // 4352 w: Q[32][68] | P1[32][68]+P2[32][68]
    float*    cqs  = (float*)(Pq + 4352);              // 1024
    float*    sA   = cqs + 1024;                       // 32 each
    float*    w2   = sA + MT2;
    float*    m1s  = w2 + MT2;
    float*    il1s = m1s + MT2;
    float*    m2s  = il1s + MT2;
    float*    il2s = m2s + MT2;

    int tid = threadIdx.x;
    int b = blockIdx.z, h = blockIdx.y, i0 = blockIdx.x * MT2;
    int bh = b*HH + h;
    size_t base = (size_t)b*LL*EE + h*DH;

    int warp = tid >> 5, lane = tid & 31;
    int gid = lane >> 2, tig = lane & 3;

    // ---- load Q tile (tf32 into Pq) + cqs + per-row scales ----
    {
        int r = tid >> 4, d = (tid & 15) * 4;
        float4 v = *(const float4*)(g_Q + base + (size_t)(i0 + r) * EE + d);
        unsigned* q = Pq + r * KSD + d;
        q[0] = f2tf32(v.x); q[1] = f2tf32(v.y); q[2] = f2tf32(v.z); q[3] = f2tf32(v.w);
    }
    for (int idx = tid; idx < 1024; idx += 512)
        cqs[idx] = g_cq[(size_t)bh*LL + idx];
    if (tid < MT2) {
        float qn = g_qn2[(size_t)(b*LL + i0 + tid)*HH + h];
        float s = rsqrtf(64.f * qn);
        sA[tid] = s;
        w2[tid] = s * rsqrtf(qn * g_cn2[bh]);
    }
    __syncthreads();

    // ---- Phase 1: S = Q @ K^T (tf32 mma), 8 j-tiles of 128, prefetched ----
    {
        int wm = warp & 1;
        int wn = warp >> 1;
        int mb = wm * 16;
        unsigned aQ[8][4];
        #pragma unroll
        for (int kc = 0; kc < 8; kc++) {
            int kk = kc * 8;
            aQ[kc][0] = Pq[(mb + gid    )*KSD + kk + tig    ];
            aQ[kc][1] = Pq[(mb + gid + 8)*KSD + kk + tig    ];
            aQ[kc][2] = Pq[(mb + gid    )*KSD + kk + tig + 4];
            aQ[kc][3] = Pq[(mb + gid + 8)*KSD + kk + tig + 4];
        }
        int r = tid >> 2, dg = (tid & 3) * 16;
        float4 pre[4];
        {
            const float* src = g_K + base + (size_t)r*EE + dg;
            #pragma unroll
            for (int c = 0; c < 4; c++) pre[c] = *(const float4*)(src + c*4);
        }
        for (int jt = 0; jt < 8; jt++) {
            unsigned* dst = Tile + r*KSD + dg;
            #pragma unroll
            for (int c = 0; c < 4; c++)
                *(uint4*)(dst + c*4) = make_uint4(f2tf32(pre[c].x), f2tf32(pre[c].y),
                                                  f2tf32(pre[c].z), f2tf32(pre[c].w));
            if (jt < 7) {
                const float* src = g_K + base + (size_t)((jt+1)*128 + r)*EE + dg;
                #pragma unroll
                for (int c = 0; c < 4; c++) pre[c] = *(const float4*)(src + c*4);
            }
            __syncthreads();
            float acc[2][4];
            #pragma unroll
            for (int nc = 0; nc < 2; nc++)
                #pragma unroll
                for (int c = 0; c < 4; c++) acc[nc][c] = 0.f;
            #pragma unroll
            for (int kc = 0; kc < 8; kc++) {
                int kk = kc * 8;
                #pragma unroll
                for (int nc = 0; nc < 2; nc++) {
                    int nb = wn*16 + nc*8;
                    unsigned b0 = Tile[(nb + gid)*KSD + kk + tig    ];
                    unsigned b1 = Tile[(nb + gid)*KSD + kk + tig + 4];
                    mma_tf32(acc[nc][0], acc[nc][1], acc[nc][2], acc[nc][3],
                             aQ[kc][0], aQ[kc][1], aQ[kc][2], aQ[kc][3], b0, b1);
                }
            }
            #pragma unroll
            for (int nc = 0; nc < 2; nc++) {
                int col = jt*128 + wn*16 + nc*8 + tig*2;
                *(float2*)&S[(mb + gid    )*SD + col] = make_float2(acc[nc][0], acc[nc][1]);
                *(float2*)&S[(mb + gid + 8)*SD + col] = make_float2(acc[nc][2], acc[nc][3]);
            }
            __syncthreads();
        }
    }

    // ---- Phase 2: dual softmax stats ----
    for (int rr = 0; rr < 2; rr++) {
        int i = warp*2 + rr;
        float sa = sA[i], ww = w2[i];
        const float* Sr = &S[i*SD];
        float m1 = -1e30f, mm2 = -1e30f;
        #pragma unroll
        for (int it = 0; it < 8; it++) {
            int j = lane*4 + it*128;
            float4 s4 = *(const float4*)&Sr[j];
            float4 c4 = *(const float4*)&cqs[j];
            m1  = fmaxf(m1,  fmaxf(fmaxf(s4.x*sa,  s4.y*sa),  fmaxf(s4.z*sa,  s4.w*sa)));
            mm2 = fmaxf(mm2, fmaxf(fmaxf(s4.x*c4.x, s4.y*c4.y), fmaxf(s4.z*c4.z, s4.w*c4.w)));
        }
        #pragma unroll
        for (int o = 16; o > 0; o >>= 1) {
            m1  = fmaxf(m1,  __shfl_xor_sync(0xffffffffu, m1,  o));
            mm2 = fmaxf(mm2, __shfl_xor_sync(0xffffffffu, mm2, o));
        }
        float m2 = mm2 * ww;
        float l1 = 0.f, l2 = 0.f;
        #pragma unroll
        for (int it = 0; it < 8; it++) {
            int j = lane*4 + it*128;
            float4 s4 = *(const float4*)&Sr[j];
            float4 c4 = *(const float4*)&cqs[j];
            l1 += __expf(s4.x*sa - m1) + __expf(s4.y*sa - m1)
                + __expf(s4.z*sa - m1) + __expf(s4.w*sa - m1);
            l2 += __expf(s4.x*c4.x*ww - m2) + __expf(s4.y*c4.y*ww - m2)
                + __expf(s4.z*c4.z*ww - m2) + __expf(s4.w*c4.w*ww - m2);
        }
        #pragma unroll
        for (int o = 16; o > 0; o >>= 1) {
            l1 += __shfl_xor_sync(0xffffffffu, l1, o);
            l2 += __shfl_xor_sync(0xffffffffu, l2, o);
        }
        if (lane == 0) { m1s[i] = m1; il1s[i] = 1.f/l1; m2s[i] = m2; il2s[i] = 1.f/l2; }
    }
    __syncthreads();

    // ---- Phase 3: warp-split  O = P1@V (warps 0-7) + P2@Cp (warps 8-15) ----
    // staging roles
    int mat   = tid >> 8;                 // 0: V/P1, 1: Cp/P2
    int dcol  = tid & 63;                 // V^T d index
    int jgrp  = (tid >> 6) & 3;           // j block-of-16 selector
    const float* gsrc3 = mat ? g_Cp : g_V;
    unsigned* myTile = Tile + mat * (64*VSD3);
    int srow = (tid >> 3) & 31;           // P staging row
    int scol = (tid & 7) * 8;             // P staging col base
    float sc_a = mat ? w2[srow]  : sA[srow];
    float m_s  = mat ? m2s[srow] : m1s[srow];
    float il_s = mat ? il2s[srow] : il1s[srow];
    unsigned* myP = Pq + mat * (32*PSD3);
    // mma roles
    int wsrc = warp >> 3;                 // 0: V, 1: Cp
    int mb3 = (warp & 1) * 16;
    int nb3 = ((warp >> 1) & 3) * 16;
    unsigned* mmaP = Pq + wsrc * (32*PSD3);
    unsigned* mmaT = Tile + wsrc * (64*VSD3);

    float acc3[2][4];
    #pragma unroll
    for (int nc = 0; nc < 2; nc++)
        #pragma unroll
        for (int c = 0; c < 4; c++) acc3[nc][c] = 0.f;

    float pre3[16];
    #pragma unroll
    for (int it = 0; it < 16; it++)
        pre3[it] = gsrc3[base + (size_t)(jgrp*16 + it)*EE + dcol];

    for (int jt = 0; jt < 16; jt++) {
        // stage V^T/Cp^T tile (uint4 stores, conflict-free phases)
        {
            unsigned* trow = myTile + dcol*VSD3 + jgrp*16;
            #pragma unroll
            for (int k4 = 0; k4 < 4; k4++)
                *(uint4*)(trow + k4*4) = make_uint4(
                    f2tf32(pre3[k4*4+0]), f2tf32(pre3[k4*4+1]),
                    f2tf32(pre3[k4*4+2]), f2tf32(pre3[k4*4+3]));
        }
        // prefetch next tile
        if (jt < 15) {
            #pragma unroll
            for (int it = 0; it < 16; it++)
                pre3[it] = gsrc3[base + (size_t)((jt+1)*64 + jgrp*16 + it)*EE + dcol];
        }
        // stage P tile; write attn for mat==0
        {
            const float* Sr = &S[srow*SD + jt*64 + scol];
            float pbuf[8];
            if (mat == 0) {
                #pragma unroll
                for (int c = 0; c < 8; c++)
                    pbuf[c] = __expf(Sr[c]*sc_a - m_s) * il_s;
                float* arow = attn_out + ((size_t)bh*LL + i0 + srow)*LL + jt*64 + scol;
                *(float4*)(arow)     = make_float4(pbuf[0], pbuf[1], pbuf[2], pbuf[3]);
                *(float4*)(arow + 4) = make_float4(pbuf[4], pbuf[5], pbuf[6], pbuf[7]);
            } else {
                const float* cr = &cqs[jt*64 + scol];
                #pragma unroll
                for (int c = 0; c < 8; c++)
                    pbuf[c] = __expf(Sr[c]*cr[c]*sc_a - m_s) * il_s;
            }
            unsigned* pd = myP + srow*PSD3 + scol;
            *(uint4*)(pd)     = make_uint4(f2tf32(pbuf[0]), f2tf32(pbuf[1]), f2tf32(pbuf[2]), f2tf32(pbuf[3]));
            *(uint4*)(pd + 4) = make_uint4(f2tf32(pbuf[4]), f2tf32(pbuf[5]), f2tf32(pbuf[6]), f2tf32(pbuf[7]));
        }
        __syncthreads();
        // mma: warp tile 16x16, K = 64
        #pragma unroll
        for (int kc = 0; kc < 8; kc++) {
            int kk = kc * 8;
            unsigned a0 = mmaP[(mb3 + gid    )*PSD3 + kk + tig    ];
            unsigned a1 = mmaP[(mb3 + gid + 8)*PSD3 + kk + tig    ];
            unsigned a2 = mmaP[(mb3 + gid    )*PSD3 + kk + tig + 4];
            unsigned a3 = mmaP[(mb3 + gid + 8)*PSD3 + kk + tig + 4];
            #pragma unroll
            for (int nc = 0; nc < 2; nc++) {
                int nb = nb3 + nc*8;
                unsigned b0 = mmaT[(nb + gid)*VSD3 + kk + tig    ];
                unsigned b1 = mmaT[(nb + gid)*VSD3 + kk + tig + 4];
                mma_tf32(acc3[nc][0], acc3[nc][1], acc3[nc][2], acc3[nc][3],
                         a0, a1, a2, a3, b0, b1);
            }
        }
        __syncthreads();
    }

    // ---- epilogue: cross-warp V+Cp reduction via S scratch ----
    if (wsrc == 1) {
        int r1 = mb3 + gid, r2 = r1 + 8;
        #pragma unroll
        for (int nc = 0; nc < 2; nc++) {
            int cc = nb3 + nc*8 + tig*2;
            *(float2*)&S[r1*KSD + cc] = make_float2(acc3[nc][0], acc3[nc][1]);
            *(float2*)&S[r2*KSD + cc] = make_float2(acc3[nc][2], acc3[nc][3]);
        }
    }
    __syncthreads();
    if (wsrc == 0) {
        int r1 = mb3 + gid, r2 = r1 + 8;
        #pragma unroll
        for (int nc = 0; nc < 2; nc++) {
            int cc = nb3 + nc*8 + tig*2;
            float2 p1 = *(const float2*)&S[r1*KSD + cc];
            float2 p2 = *(const float2*)&S[r2*KSD + cc];
            *(float2*)&g_vals[((size_t)b*SS + 1 + i0 + r1)*EE + h*DH + cc] =
                make_float2(acc3[nc][0] + p1.x, acc3[nc][1] + p1.y);
            *(float2*)&g_vals[((size_t)b*SS + 1 + i0 + r2)*EE + h*DH + cc] =
                make_float2(acc3[nc][2] + p2.x, acc3[nc][3] + p2.y);
        }
    }
}

// ---------------- launch ----------------------------------------------------
extern "C" void kernel_launch(void* const* d_in, const int* in_sizes, int n_in,
                              void* d_out, int out_size)
{
    const float* x  = (const float*)d_in[0];
    const float* Wq = (const float*)d_in[1];
    const float* bq = (const float*)d_in[2];
    const float* Wk = (const float*)d_in[3];
    const float* bk = (const float*)d_in[4];
    const float* Wv = (const float*)d_in[5];
    const float* bv = (const float*)d_in[6];
    const float* Wo = (const float*)d_in[7];
    const float* bo = (const float*)d_in[8];
    const float* Wc = (const float*)d_in[9];
    const float* bc = (const float*)d_in[10];

    float* out  = (float*)d_out;                      // (B,1025,E)
    float* attn = out + (size_t)Bb*SS*EE;             // (B,H,1024,1024)

    float* dVals;
    cudaGetSymbolAddress((void**)&dVals, g_vals);

    const int SMEM_BYTES = (MT2*SD + 8704 + 4352 + 1024 + 6*MT2) * sizeof(float);
    cudaFuncSetAttribute(attn_mma, cudaFuncAttributeMaxDynamicSharedMemorySize, SMEM_BYTES);

    proj4_tf32<<<dim3(32, 64), 256>>>(x, Wq, bq, Wk, bk, Wv, bv, Wc, bc);

    cls_proj_kernel<<<16, 256>>>(x, Wq, bq);
    cn2_kernel<<<1, 64>>>();
    qn2_kernel<<<256, 256>>>();
    cq_kernel<<<256, 256>>>();
    o2c_kernel<<<dim3(HH, Bb), 256>>>();

    attn_mma<<<dim3(LL/MT2, HH, Bb), 512, SMEM_BYTES>>>(attn);

    sgemmo_tf32<<<dim3(33, 16), 256>>>(dVals, Wo, bo, out);
}

// round 9
// speedup vs baseline: 3.7660x; 1.0081x over previous
#include <cuda_runtime.h>
#include <cuda_bf16.h>
#include <math.h>

#define Bb 4
#define SS 1025
#define LL 1024
#define EE 1024
#define HH 16
#define DH 64
#define EPSV 1e-5f

#define MT2 32          // attention rows per block
#define SDB 1064        // S row stride in bf16 elements (conflict-free)
#define KSD 68          // K tile stride (phase 1, [j][d])
#define VSD3 68         // Vt/Ct tile stride (phase 3, [d][j])
#define PSD3 68         // P tile stride (phase 3, [i][j])
#define SWORDS 17024    // S region in float words (32*1064*2B/4)
#define TILE_W 8704     // words per Tile buffer
#define PQ_W 4352       // words per Pq buffer

// ---------------- scratch (static device globals; no allocs allowed) -------
__device__ float g_Q [Bb*LL*EE];
__device__ float g_K [Bb*LL*EE];
__device__ float g_V [Bb*LL*EE];
__device__ float g_Cp[Bb*LL*EE];
__device__ float g_vals[Bb*SS*EE];
__device__ float g_qn2[Bb*LL*HH];
__device__ float g_c  [Bb*EE];
__device__ float g_cn2[Bb*HH];
__device__ float g_cq [Bb*HH*LL];

// ---------------- tf32 helpers ---------------------------------------------
__device__ __forceinline__ unsigned f2tf32(float x) {
    unsigned r;
    asm("cvt.rna.tf32.f32 %0, %1;" : "=r"(r) : "f"(x));
    return r;
}

__device__ __forceinline__ void mma_tf32(float& c0, float& c1, float& c2, float& c3,
                                         unsigned a0, unsigned a1, unsigned a2, unsigned a3,
                                         unsigned b0, unsigned b1)
{
    asm volatile("mma.sync.aligned.m16n8k8.row.col.f32.tf32.tf32.f32 "
                 "{%0,%1,%2,%3}, {%4,%5,%6,%7}, {%8,%9}, {%0,%1,%2,%3};"
                 : "+f"(c0), "+f"(c1), "+f"(c2), "+f"(c3)
                 : "r"(a0), "r"(a1), "r"(a2), "r"(a3), "r"(b0), "r"(b1));
}

// ---------------- fused Q/K/V/Cp projections (tf32 tensor core) ------------
__global__ __launch_bounds__(256) void proj4_tf32(
    const float* __restrict__ x,
    const float* __restrict__ Wq, const float* __restrict__ bq,
    const float* __restrict__ Wk, const float* __restrict__ bk,
    const float* __restrict__ Wv, const float* __restrict__ bv,
    const float* __restrict__ Wc, const float* __restrict__ bc)
{
    __shared__ unsigned As[128][36];
    __shared__ unsigned Bs[64][36];

    int tid = threadIdx.x;
    int m0 = blockIdx.x * 128;
    int y  = blockIdx.y;
    int which = y >> 4;
    int n0 = (y & 15) * 64;

    const float* W; const float* bias; float* dst;
    switch (which) {
        case 0:  W = Wq; bias = bq; dst = g_Q;  break;
        case 1:  W = Wk; bias = bk; dst = g_K;  break;
        case 2:  W = Wv; bias = bv; dst = g_V;  break;
        default: W = Wc; bias = bc; dst = g_Cp; break;
    }

    int warp = tid >> 5, lane = tid & 31;
    int wm = warp >> 1, wn = warp & 1;
    int gid = lane >> 2, tig = lane & 3;

    float acc[2][4][4];
    #pragma unroll
    for (int mi = 0; mi < 2; mi++)
        #pragma unroll
        for (int ni = 0; ni < 4; ni++)
            #pragma unroll
            for (int c = 0; c < 4; c++) acc[mi][ni][c] = 0.f;

    int lr = tid >> 3;
    int lk = (tid & 7) * 4;

    for (int k0 = 0; k0 < EE; k0 += 32) {
        #pragma unroll
        for (int r = 0; r < 4; r++) {
            int m = m0 + lr + r * 32;
            int b = m >> 10, t = m & 1023;
            float4 v = *(const float4*)(x + (size_t)(b * SS + t + 1) * EE + k0 + lk);
            As[lr + r * 32][lk + 0] = f2tf32(v.x);
            As[lr + r * 32][lk + 1] = f2tf32(v.y);
            As[lr + r * 32][lk + 2] = f2tf32(v.z);
            As[lr + r * 32][lk + 3] = f2tf32(v.w);
        }
        #pragma unroll
        for (int r = 0; r < 2; r++) {
            float4 v = *(const float4*)(W + (size_t)(n0 + lr + r * 32) * EE + k0 + lk);
            Bs[lr + r * 32][lk + 0] = f2tf32(v.x);
            Bs[lr + r * 32][lk + 1] = f2tf32(v.y);
            Bs[lr + r * 32][lk + 2] = f2tf32(v.z);
            Bs[lr + r * 32][lk + 3] = f2tf32(v.w);
        }
        __syncthreads();

        #pragma unroll
        for (int kk = 0; kk < 32; kk += 8) {
            unsigned a[2][4], bfr[4][2];
            #pragma unroll
            for (int mi = 0; mi < 2; mi++) {
                int mb = wm * 32 + mi * 16;
                a[mi][0] = As[mb + gid    ][kk + tig    ];
                a[mi][1] = As[mb + gid + 8][kk + tig    ];
                a[mi][2] = As[mb + gid    ][kk + tig + 4];
                a[mi][3] = As[mb + gid + 8][kk + tig + 4];
            }
            #pragma unroll
            for (int ni = 0; ni < 4; ni++) {
                int nb = wn * 32 + ni * 8;
                bfr[ni][0] = Bs[nb + gid][kk + tig    ];
                bfr[ni][1] = Bs[nb + gid][kk + tig + 4];
            }
            #pragma unroll
            for (int mi = 0; mi < 2; mi++)
                #pragma unroll
                for (int ni = 0; ni < 4; ni++)
                    mma_tf32(acc[mi][ni][0], acc[mi][ni][1], acc[mi][ni][2], acc[mi][ni][3],
                             a[mi][0], a[mi][1], a[mi][2], a[mi][3],
                             bfr[ni][0], bfr[ni][1]);
        }
        __syncthreads();
    }

    #pragma unroll
    for (int mi = 0; mi < 2; mi++) {
        int row1 = m0 + wm * 32 + mi * 16 + gid;
        int row2 = row1 + 8;
        #pragma unroll
        for (int ni = 0; ni < 4; ni++) {
            int col = n0 + wn * 32 + ni * 8 + tig * 2;
            float b0v = bias[col], b1v = bias[col + 1];
            float2 o1 = make_float2(acc[mi][ni][0] + b0v, acc[mi][ni][1] + b1v);
            float2 o2 = make_float2(acc[mi][ni][2] + b0v, acc[mi][ni][3] + b1v);
            *(float2*)(dst + (size_t)row1 * EE + col) = o1;
            *(float2*)(dst + (size_t)row2 * EE + col) = o2;
        }
    }
}

// ---------------- tf32 output projection: out = vals @ Wo^T + bo ------------
__global__ __launch_bounds__(256) void sgemmo_tf32(
    const float* __restrict__ A,
    const float* __restrict__ W,
    const float* __restrict__ bias,
    float* __restrict__ Y)
{
    const int M = Bb * SS;   // 4100
    __shared__ unsigned As[128][36];
    __shared__ unsigned Bs[64][36];

    int tid = threadIdx.x;
    int m0 = blockIdx.x * 128;
    int n0 = blockIdx.y * 64;

    int warp = tid >> 5, lane = tid & 31;
    int wm = warp >> 1, wn = warp & 1;
    int gid = lane >> 2, tig = lane & 3;

    float acc[2][4][4];
    #pragma unroll
    for (int mi = 0; mi < 2; mi++)
        #pragma unroll
        for (int ni = 0; ni < 4; ni++)
            #pragma unroll
            for (int c = 0; c < 4; c++) acc[mi][ni][c] = 0.f;

    int lr = tid >> 3;
    int lk = (tid & 7) * 4;

    for (int k0 = 0; k0 < EE; k0 += 32) {
        #pragma unroll
        for (int r = 0; r < 4; r++) {
            int m = m0 + lr + r * 32;
            float4 v = (m < M) ? *(const float4*)(A + (size_t)m * EE + k0 + lk)
                               : make_float4(0.f, 0.f, 0.f, 0.f);
            As[lr + r * 32][lk + 0] = f2tf32(v.x);
            As[lr + r * 32][lk + 1] = f2tf32(v.y);
            As[lr + r * 32][lk + 2] = f2tf32(v.z);
            As[lr + r * 32][lk + 3] = f2tf32(v.w);
        }
        #pragma unroll
        for (int r = 0; r < 2; r++) {
            float4 v = *(const float4*)(W + (size_t)(n0 + lr + r * 32) * EE + k0 + lk);
            Bs[lr + r * 32][lk + 0] = f2tf32(v.x);
            Bs[lr + r * 32][lk + 1] = f2tf32(v.y);
            Bs[lr + r * 32][lk + 2] = f2tf32(v.z);
            Bs[lr + r * 32][lk + 3] = f2tf32(v.w);
        }
        __syncthreads();

        #pragma unroll
        for (int kk = 0; kk < 32; kk += 8) {
            unsigned a[2][4], bfr[4][2];
            #pragma unroll
            for (int mi = 0; mi < 2; mi++) {
                int mb = wm * 32 + mi * 16;
                a[mi][0] = As[mb + gid    ][kk + tig    ];
                a[mi][1] = As[mb + gid + 8][kk + tig    ];
                a[mi][2] = As[mb + gid    ][kk + tig + 4];
                a[mi][3] = As[mb + gid + 8][kk + tig + 4];
            }
            #pragma unroll
            for (int ni = 0; ni < 4; ni++) {
                int nb = wn * 32 + ni * 8;
                bfr[ni][0] = Bs[nb + gid][kk + tig    ];
                bfr[ni][1] = Bs[nb + gid][kk + tig + 4];
            }
            #pragma unroll
            for (int mi = 0; mi < 2; mi++)
                #pragma unroll
                for (int ni = 0; ni < 4; ni++)
                    mma_tf32(acc[mi][ni][0], acc[mi][ni][1], acc[mi][ni][2], acc[mi][ni][3],
                             a[mi][0], a[mi][1], a[mi][2], a[mi][3],
                             bfr[ni][0], bfr[ni][1]);
        }
        __syncthreads();
    }

    #pragma unroll
    for (int mi = 0; mi < 2; mi++) {
        int row1 = m0 + wm * 32 + mi * 16 + gid;
        int row2 = row1 + 8;
        #pragma unroll
        for (int ni = 0; ni < 4; ni++) {
            int col = n0 + wn * 32 + ni * 8 + tig * 2;
            float b0v = bias[col], b1v = bias[col + 1];
            if (row1 < M)
                *(float2*)(Y + (size_t)row1 * EE + col) =
                    make_float2(acc[mi][ni][0] + b0v, acc[mi][ni][1] + b1v);
            if (row2 < M)
                *(float2*)(Y + (size_t)row2 * EE + col) =
                    make_float2(acc[mi][ni][2] + b0v, acc[mi][ni][3] + b1v);
        }
    }
}

// ---------------- small kernels ---------------------------------------------
__global__ void cls_proj_kernel(const float* __restrict__ x,
                                const float* __restrict__ Wq,
                                const float* __restrict__ bq)
{
    int idx = blockIdx.x * blockDim.x + threadIdx.x;
    int b = idx >> 10, n = idx & 1023;
    const float* xr = x + (size_t)b*SS*EE;
    const float* wr = Wq + (size_t)n*EE;
    float s = 0.f;
    for (int k = 0; k < EE; k += 4) {
        float4 xv = *(const float4*)(xr + k);
        float4 wv = *(const float4*)(wr + k);
        s += xv.x*wv.x + xv.y*wv.y + xv.z*wv.z + xv.w*wv.w;
    }
    g_c[idx] = s + bq[n];
}

__global__ void cn2_kernel()
{
    int t = threadIdx.x;
    const float* c = g_c + (t >> 4)*EE + (t & 15)*DH;
    float s = 0.f;
    #pragma unroll
    for (int d = 0; d < DH; d++) s += c[d]*c[d];
    g_cn2[t] = fmaxf(s, EPSV);
}

__global__ void qn2_kernel()
{
    int idx = blockIdx.x * blockDim.x + threadIdx.x;
    int bt = idx >> 4, h = idx & 15;
    const float* q = g_Q + (size_t)bt*EE + h*DH;
    float s = 0.f;
    #pragma unroll
    for (int d = 0; d < DH; d += 4) {
        float4 v = *(const float4*)(q + d);
        s += v.x*v.x + v.y*v.y + v.z*v.z + v.w*v.w;
    }
    g_qn2[idx] = fmaxf(s, EPSV);
}

__global__ void cq_kernel()
{
    int idx = blockIdx.x * blockDim.x + threadIdx.x;
    int bh = idx >> 10, j = idx & 1023;
    int b = bh >> 4, h = bh & 15;
    const float* c = g_c + (size_t)b*EE + h*DH;
    const float* q = g_Q + (size_t)(b*LL + j)*EE + h*DH;
    float s = 0.f;
    #pragma unroll
    for (int d = 0; d < DH; d += 4) {
        float4 cv = *(const float4*)(c + d);
        float4 qv = *(const float4*)(q + d);
        s += cv.x*qv.x + cv.y*qv.y + cv.z*qv.z + cv.w*qv.w;
    }
    g_cq[idx] = s;
}

__global__ void o2c_kernel()
{
    __shared__ float cs[64];
    __shared__ float ck[1024];
    __shared__ float red[256];
    int h = blockIdx.x, b = blockIdx.y;
    int bh = b*HH + h;
    int tid = threadIdx.x;

    if (tid < 64) cs[tid] = g_c[(size_t)b*EE + h*DH + tid];
    __syncthreads();

    float scale = rsqrtf(64.f * g_cn2[bh]);
    for (int j = tid; j < 1024; j += 256) {
        const float* kr = g_K + (size_t)(b*LL + j)*EE + h*DH;
        float s = 0.f;
        #pragma unroll
        for (int d = 0; d < DH; d += 4) {
            float4 cv = *(const float4*)(cs + d);
            float4 kv = *(const float4*)(kr + d);
            s += cv.x*kv.x + cv.y*kv.y + cv.z*kv.z + cv.w*kv.w;
        }
        ck[j] = s * scale;
    }
    __syncthreads();

    float m = -1e30f;
    for (int j = tid; j < 1024; j += 256) m = fmaxf(m, ck[j]);
    red[tid] = m; __syncthreads();
    for (int s = 128; s > 0; s >>= 1) { if (tid < s) red[tid] = fmaxf(red[tid], red[tid+s]); __syncthreads(); }
    m = red[0]; __syncthreads();

    float l = 0.f;
    for (int j = tid; j < 1024; j += 256) { float e = __expf(ck[j] - m); ck[j] = e; l += e; }
    red[tid] = l; __syncthreads();
    for (int s = 128; s > 0; s >>= 1) { if (tid < s) red[tid] += red[tid+s]; __syncthreads(); }
    l = red[0]; __syncthreads();
    float invl = 1.f / l;

    int d = tid & 63, part = tid >> 6;
    float s = 0.f;
    for (int j = part; j < 1024; j += 4)
        s += ck[j] * g_V[(size_t)(b*LL + j)*EE + h*DH + d];
    red[tid] = s; __syncthreads();
    if (part == 0) {
        float tot = red[d] + red[64+d] + red[128+d] + red[192+d];
        g_vals[(size_t)b*SS*EE + h*DH + d] = tot * invl;
    }
}

// ---------------- fused attention core (bf16 S, double-buffered) ------------
__global__ __launch_bounds__(512) void attn_mma(float* __restrict__ attn_out)
{
    extern __shared__ float sm[];
    __nv_bfloat16* Sb = (__nv_bfloat16*)sm;            // [32][SDB] bf16
    unsigned* Tile0 = (unsigned*)(sm + SWORDS);        // two Tile buffers
    unsigned* Tile1 = Tile0 + TILE_W;
    unsigned* Pq0   = Tile1 + TILE_W;                  // two Pq buffers
    unsigned* Pq1   = Pq0 + PQ_W;
    float*    cqs  = (float*)(Pq1 + PQ_W);             // 1024
    float*    sA   = cqs + 1024;                       // 32 each
    float*    w2   = sA + MT2;
    float*    m1s  = w2 + MT2;
    float*    il1s = m1s + MT2;
    float*    m2s  = il1s + MT2;
    float*    il2s = m2s + MT2;

    int tid = threadIdx.x;
    int b = blockIdx.z, h = blockIdx.y, i0 = blockIdx.x * MT2;
    int bh = b*HH + h;
    size_t base = (size_t)b*LL*EE + h*DH;

    int warp = tid >> 5, lane = tid & 31;
    int gid = lane >> 2, tig = lane & 3;

    // ---- load Q tile (tf32 into Pq0) + cqs + per-row scales ----
    {
        int r = tid >> 4, d = (tid & 15) * 4;
        float4 v = *(const float4*)(g_Q + base + (size_t)(i0 + r) * EE + d);
        unsigned* q = Pq0 + r * KSD + d;
        q[0] = f2tf32(v.x); q[1] = f2tf32(v.y); q[2] = f2tf32(v.z); q[3] = f2tf32(v.w);
    }
    for (int idx = tid; idx < 1024; idx += 512)
        cqs[idx] = g_cq[(size_t)bh*LL + idx];
    if (tid < MT2) {
        float qn = g_qn2[(size_t)(b*LL + i0 + tid)*HH + h];
        float s = rsqrtf(64.f * qn);
        sA[tid] = s;
        w2[tid] = s * rsqrtf(qn * g_cn2[bh]);
    }
    __syncthreads();

    // ---- Phase 1: S = Q @ K^T (tf32 mma), 8 j-tiles of 128, double-buffered
    {
        int wm = warp & 1;
        int wn = warp >> 1;
        int mb = wm * 16;
        unsigned aQ[8][4];
        #pragma unroll
        for (int kc = 0; kc < 8; kc++) {
            int kk = kc * 8;
            aQ[kc][0] = Pq0[(mb + gid    )*KSD + kk + tig    ];
            aQ[kc][1] = Pq0[(mb + gid + 8)*KSD + kk + tig    ];
            aQ[kc][2] = Pq0[(mb + gid    )*KSD + kk + tig + 4];
            aQ[kc][3] = Pq0[(mb + gid + 8)*KSD + kk + tig + 4];
        }
        int r = tid >> 2, dg = (tid & 3) * 16;
        float4 pre[4];
        {
            const float* src = g_K + base + (size_t)r*EE + dg;
            #pragma unroll
            for (int c = 0; c < 4; c++) pre[c] = *(const float4*)(src + c*4);
        }
        for (int jt = 0; jt < 8; jt++) {
            unsigned* Tb = (jt & 1) ? Tile1 : Tile0;
            unsigned* dst = Tb + r*KSD + dg;
            #pragma unroll
            for (int c = 0; c < 4; c++)
                *(uint4*)(dst + c*4) = make_uint4(f2tf32(pre[c].x), f2tf32(pre[c].y),
                                                  f2tf32(pre[c].z), f2tf32(pre[c].w));
            if (jt < 7) {
                const float* src = g_K + base + (size_t)((jt+1)*128 + r)*EE + dg;
                #pragma unroll
                for (int c = 0; c < 4; c++) pre[c] = *(const float4*)(src + c*4);
            }
            __syncthreads();
            float acc[2][4];
            #pragma unroll
            for (int nc = 0; nc < 2; nc++)
                #pragma unroll
                for (int c = 0; c < 4; c++) acc[nc][c] = 0.f;
            #pragma unroll
            for (int kc = 0; kc < 8; kc++) {
                int kk = kc * 8;
                #pragma unroll
                for (int nc = 0; nc < 2; nc++) {
                    int nb = wn*16 + nc*8;
                    unsigned b0 = Tb[(nb + gid)*KSD + kk + tig    ];
                    unsigned b1 = Tb[(nb + gid)*KSD + kk + tig + 4];
                    mma_tf32(acc[nc][0], acc[nc][1], acc[nc][2], acc[nc][3],
                             aQ[kc][0], aQ[kc][1], aQ[kc][2], aQ[kc][3], b0, b1);
                }
            }
            #pragma unroll
            for (int nc = 0; nc < 2; nc++) {
                int col = jt*128 + wn*16 + nc*8 + tig*2;
                *(__nv_bfloat162*)&Sb[(mb + gid    )*SDB + col] =
                    __floats2bfloat162_rn(acc[nc][0], acc[nc][1]);
                *(__nv_bfloat162*)&Sb[(mb + gid + 8)*SDB + col] =
                    __floats2bfloat162_rn(acc[nc][2], acc[nc][3]);
            }
            // no trailing sync (next STS targets the other buffer)
        }
    }
    __syncthreads();

    // ---- Phase 2: dual softmax stats (bf16 S scan) ----
    for (int rr = 0; rr < 2; rr++) {
        int i = warp*2 + rr;
        float sa = sA[i], ww = w2[i];
        const __nv_bfloat16* Sr = Sb + (size_t)i*SDB;
        float m1 = -1e30f, mm2 = -1e30f;
        #pragma unroll
        for (int it = 0; it < 4; it++) {
            int j = lane*8 + it*256;
            uint4 sv = *(const uint4*)&Sr[j];
            float2 f0 = __bfloat1622float2(*(__nv_bfloat162*)&sv.x);
            float2 f1 = __bfloat1622float2(*(__nv_bfloat162*)&sv.y);
            float2 f2 = __bfloat1622float2(*(__nv_bfloat162*)&sv.z);
            float2 f3 = __bfloat1622float2(*(__nv_bfloat162*)&sv.w);
            float4 c0 = *(const float4*)&cqs[j];
            float4 c1 = *(const float4*)&cqs[j+4];
            m1 = fmaxf(m1, fmaxf(fmaxf(f0.x*sa, f0.y*sa), fmaxf(f1.x*sa, f1.y*sa)));
            m1 = fmaxf(m1, fmaxf(fmaxf(f2.x*sa, f2.y*sa), fmaxf(f3.x*sa, f3.y*sa)));
            mm2 = fmaxf(mm2, fmaxf(fmaxf(f0.x*c0.x, f0.y*c0.y), fmaxf(f1.x*c0.z, f1.y*c0.w)));
            mm2 = fmaxf(mm2, fmaxf(fmaxf(f2.x*c1.x, f2.y*c1.y), fmaxf(f3.x*c1.z, f3.y*c1.w)));
        }
        #pragma unroll
        for (int o = 16; o > 0; o >>= 1) {
            m1  = fmaxf(m1,  __shfl_xor_sync(0xffffffffu, m1,  o));
            mm2 = fmaxf(mm2, __shfl_xor_sync(0xffffffffu, mm2, o));
        }
        float m2 = mm2 * ww;
        float l1 = 0.f, l2 = 0.f;
        #pragma unroll
        for (int it = 0; it < 4; it++) {
            int j = lane*8 + it*256;
            uint4 sv = *(const uint4*)&Sr[j];
            float2 f0 = __bfloat1622float2(*(__nv_bfloat162*)&sv.x);
            float2 f1 = __bfloat1622float2(*(__nv_bfloat162*)&sv.y);
            float2 f2 = __bfloat1622float2(*(__nv_bfloat162*)&sv.z);
            float2 f3 = __bfloat1622float2(*(__nv_bfloat162*)&sv.w);
            float4 c0 = *(const float4*)&cqs[j];
            float4 c1 = *(const float4*)&cqs[j+4];
            l1 += __expf(f0.x*sa - m1) + __expf(f0.y*sa - m1)
                + __expf(f1.x*sa - m1) + __expf(f1.y*sa - m1)
                + __expf(f2.x*sa - m1) + __expf(f2.y*sa - m1)
                + __expf(f3.x*sa - m1) + __expf(f3.y*sa - m1);
            l2 += __expf(f0.x*c0.x*ww - m2) + __expf(f0.y*c0.y*ww - m2)
                + __expf(f1.x*c0.z*ww - m2) + __expf(f1.y*c0.w*ww - m2)
                + __expf(f2.x*c1.x*ww - m2) + __expf(f2.y*c1.y*ww - m2)
                + __expf(f3.x*c1.z*ww - m2) + __expf(f3.y*c1.w*ww - m2);
        }
        #pragma unroll
        for (int o = 16; o > 0; o >>= 1) {
            l1 += __shfl_xor_sync(0xffffffffu, l1, o);
            l2 += __shfl_xor_sync(0xffffffffu, l2, o);
        }
        if (lane == 0) { m1s[i] = m1; il1s[i] = 1.f/l1; m2s[i] = m2; il2s[i] = 1.f/l2; }
    }
    __syncthreads();

    // ---- Phase 3: warp-split, double-buffered  O = P1@V + P2@Cp ----
    int mat   = tid >> 8;                 // 0: V/P1, 1: Cp/P2
    int dcol  = tid & 63;
    int jgrp  = (tid >> 6) & 3;
    const float* gsrc3 = mat ? g_Cp : g_V;
    int srow = (tid >> 3) & 31;
    int scol = (tid & 7) * 8;
    float sc_a = mat ? w2[srow]  : sA[srow];
    float m_s  = mat ? m2s[srow] : m1s[srow];
    float il_s = mat ? il2s[srow] : il1s[srow];
    int wsrc = warp >> 3;
    int mb3 = (warp & 1) * 16;
    int nb3 = ((warp >> 1) & 3) * 16;

    float acc3[2][4];
    #pragma unroll
    for (int nc = 0; nc < 2; nc++)
        #pragma unroll
        for (int c = 0; c < 4; c++) acc3[nc][c] = 0.f;

    float pre3[16];
    #pragma unroll
    for (int it = 0; it < 16; it++)
        pre3[it] = gsrc3[base + (size_t)(jgrp*16 + it)*EE + dcol];

    for (int jt = 0; jt < 16; jt++) {
        unsigned* TbB = (jt & 1) ? Tile1 : Tile0;
        unsigned* PqB = (jt & 1) ? Pq1 : Pq0;
        // stage V^T/Cp^T tile
        {
            unsigned* trow = TbB + mat*(64*VSD3) + dcol*VSD3 + jgrp*16;
            #pragma unroll
            for (int k4 = 0; k4 < 4; k4++)
                *(uint4*)(trow + k4*4) = make_uint4(
                    f2tf32(pre3[k4*4+0]), f2tf32(pre3[k4*4+1]),
                    f2tf32(pre3[k4*4+2]), f2tf32(pre3[k4*4+3]));
        }
        if (jt < 15) {
            #pragma unroll
            for (int it = 0; it < 16; it++)
                pre3[it] = gsrc3[base + (size_t)((jt+1)*64 + jgrp*16 + it)*EE + dcol];
        }
        // stage P tile from bf16 S; write attn for mat==0
        {
            uint4 raw = *(const uint4*)&Sb[(size_t)srow*SDB + jt*64 + scol];
            float2 f0 = __bfloat1622float2(*(__nv_bfloat162*)&raw.x);
            float2 f1 = __bfloat1622float2(*(__nv_bfloat162*)&raw.y);
            float2 f2 = __bfloat1622float2(*(__nv_bfloat162*)&raw.z);
            float2 f3 = __bfloat1622float2(*(__nv_bfloat162*)&raw.w);
            float rv[8] = {f0.x, f0.y, f1.x, f1.y, f2.x, f2.y, f3.x, f3.y};
            float pbuf[8];
            if (mat == 0) {
                #pragma unroll
                for (int c = 0; c < 8; c++)
                    pbuf[c] = __expf(rv[c]*sc_a - m_s) * il_s;
                float* arow = attn_out + ((size_t)bh*LL + i0 + srow)*LL + jt*64 + scol;
                *(float4*)(arow)     = make_float4(pbuf[0], pbuf[1], pbuf[2], pbuf[3]);
                *(float4*)(arow + 4) = make_float4(pbuf[4], pbuf[5], pbuf[6], pbuf[7]);
            } else {
                const float* cr = &cqs[jt*64 + scol];
                #pragma unroll
                for (int c = 0; c < 8; c++)
                    pbuf[c] = __expf(rv[c]*cr[c]*sc_a - m_s) * il_s;
            }
            unsigned* pd = PqB + mat*(32*PSD3) + srow*PSD3 + scol;
            *(uint4*)(pd)     = make_uint4(f2tf32(pbuf[0]), f2tf32(pbuf[1]), f2tf32(pbuf[2]), f2tf32(pbuf[3]));
            *(uint4*)(pd + 4) = make_uint4(f2tf32(pbuf[4]), f2tf32(pbuf[5]), f2tf32(pbuf[6]), f2tf32(pbuf[7]));
        }
        __syncthreads();
        // mma: warp tile 16x16, K = 64
        unsigned* mmaP = PqB + wsrc*(32*PSD3);
        unsigned* mmaT = TbB + wsrc*(64*VSD3);
        #pragma unroll
        for (int kc = 0; kc < 8; kc++) {
            int kk = kc * 8;
            unsigned a0 = mmaP[(mb3 + gid    )*PSD3 + kk + tig    ];
            unsigned a1 = mmaP[(mb3 + gid + 8)*PSD3 + kk + tig    ];
            unsigned a2 = mmaP[(mb3 + gid    )*PSD3 + kk + tig + 4];
            unsigned a3 = mmaP[(mb3 + gid + 8)*PSD3 + kk + tig + 4];
            #pragma unroll
            for (int nc = 0; nc < 2; nc++) {
                int nb = nb3 + nc*8;
                unsigned b0 = mmaT[(nb + gid)*VSD3 + kk + tig    ];
                unsigned b1 = mmaT[(nb + gid)*VSD3 + kk + tig + 4];
                mma_tf32(acc3[nc][0], acc3[nc][1], acc3[nc][2], acc3[nc][3],
                         a0, a1, a2, a3, b0, b1);
            }
        }
        // no trailing sync (next STS targets the other buffer)
    }

    // ---- epilogue: cross-warp V+Cp reduction via fp32 scratch in Tile0 ----
    __syncthreads();
    float* scr = (float*)Tile0;     // [32][68] fp32
    if (wsrc == 1) {
        int r1 = mb3 + gid, r2 = r1 + 8;
        #pragma unroll
        for (int nc = 0; nc < 2; nc++) {
            int cc = nb3 + nc*8 + tig*2;
            *(float2*)&scr[r1*KSD + cc] = make_float2(acc3[nc][0], acc3[nc][1]);
            *(float2*)&scr[r2*KSD + cc] = make_float2(acc3[nc][2], acc3[nc][3]);
        }
    }
    __syncthreads();
    if (wsrc == 0) {
        int r1 = mb3 + gid, r2 = r1 + 8;
        #pragma unroll
        for (int nc = 0; nc < 2; nc++) {
            int cc = nb3 + nc*8 + tig*2;
            float2 p1 = *(const float2*)&scr[r1*KSD + cc];
            float2 p2 = *(const float2*)&scr[r2*KSD + cc];
            *(float2*)&g_vals[((size_t)b*SS + 1 + i0 + r1)*EE + h*DH + cc] =
                make_float2(acc3[nc][0] + p1.x, acc3[nc][1] + p1.y);
            *(float2*)&g_vals[((size_t)b*SS + 1 + i0 + r2)*EE + h*DH + cc] =
                make_float2(acc3[nc][2] + p2.x, acc3[nc][3] + p2.y);
        }
    }
}

// ---------------- launch ----------------------------------------------------
extern "C" void kernel_launch(void* const* d_in, const int* in_sizes, int n_in,
                              void* d_out, int out_size)
{
    const float* x  = (const float*)d_in[0];
    const float* Wq = (const float*)d_in[1];
    const float* bq = (const float*)d_in[2];
    const float* Wk = (const float*)d_in[3];
    const float* bk = (const float*)d_in[4];
    const float* Wv = (const float*)d_in[5];
    const float* bv = (const float*)d_in[6];
    const float* Wo = (const float*)d_in[7];
    const float* bo = (const float*)d_in[8];
    const float* Wc = (const float*)d_in[9];
    const float* bc = (const float*)d_in[10];

    float* out  = (float*)d_out;                      // (B,1025,E)
    float* attn = out + (size_t)Bb*SS*EE;             // (B,H,1024,1024)

    float* dVals;
    cudaGetSymbolAddress((void**)&dVals, g_vals);

    const int SMEM_BYTES = (SWORDS + 2*TILE_W + 2*PQ_W + 1024 + 6*MT2) * sizeof(float);
    cudaFuncSetAttribute(attn_mma, cudaFuncAttributeMaxDynamicSharedMemorySize, SMEM_BYTES);

    proj4_tf32<<<dim3(32, 64), 256>>>(x, Wq, bq, Wk, bk, Wv, bv, Wc, bc);

    cls_proj_kernel<<<16, 256>>>(x, Wq, bq);
    cn2_kernel<<<1, 64>>>();
    qn2_kernel<<<256, 256>>>();
    cq_kernel<<<256, 256>>>();
    o2c_kernel<<<dim3(HH, Bb), 256>>>();

    attn_mma<<<dim3(LL/MT2, HH, Bb), 512, SMEM_BYTES>>>(attn);

    sgemmo_tf32<<<dim3(33, 16), 256>>>(dVals, Wo, bo, out);
}